// round 1
// baseline (speedup 1.0000x reference)
#include <cuda_runtime.h>
#include <math.h>

// Problem constants
#define Hdim 1024
#define NH   16
#define DH   64
#define Bb   2
#define Ss   2048
#define MT   (Bb * Ss)   // 4096 rows

// Scratch (no allocations allowed -> __device__ globals), 16 MB each
__device__ float g_q[MT * Hdim];
__device__ float g_k[MT * Hdim];
__device__ float g_v[MT * Hdim];
__device__ float g_o[MT * Hdim];

// ---------------------------------------------------------------------------
// GEMM: out[M,N] = A[M,K] @ W[N,K]^T + bias[N]   (M=4096, N=K=1024)
// 128x128 block tile, BK=8, 256 threads, 8x8 per-thread micro-tile.
// ---------------------------------------------------------------------------
__global__ void __launch_bounds__(256) sgemm_bias_k(
    const float* __restrict__ A, const float* __restrict__ W,
    const float* __restrict__ bias, float* __restrict__ out)
{
    const int K = Hdim, N = Hdim;
    __shared__ float As[8 * 128];
    __shared__ float Bs[8 * 128];

    const int tid = threadIdx.x;
    const int tx = tid & 15, ty = tid >> 4;
    const int m0 = blockIdx.y * 128, n0 = blockIdx.x * 128;

    const int lrow = tid >> 1;
    const int lkg  = (tid & 1) * 4;
    const float* Ap = A + (size_t)(m0 + lrow) * K + lkg;
    const float* Wp = W + (size_t)(n0 + lrow) * K + lkg;

    float acc[8][8];
#pragma unroll
    for (int i = 0; i < 8; i++)
#pragma unroll
        for (int j = 0; j < 8; j++) acc[i][j] = 0.0f;

    for (int k0 = 0; k0 < K; k0 += 8) {
        float4 av = *(const float4*)(Ap + k0);
        float4 wv = *(const float4*)(Wp + k0);
        As[(lkg + 0) * 128 + lrow] = av.x;
        As[(lkg + 1) * 128 + lrow] = av.y;
        As[(lkg + 2) * 128 + lrow] = av.z;
        As[(lkg + 3) * 128 + lrow] = av.w;
        Bs[(lkg + 0) * 128 + lrow] = wv.x;
        Bs[(lkg + 1) * 128 + lrow] = wv.y;
        Bs[(lkg + 2) * 128 + lrow] = wv.z;
        Bs[(lkg + 3) * 128 + lrow] = wv.w;
        __syncthreads();

#pragma unroll
        for (int kk = 0; kk < 8; kk++) {
            float4 a0 = *(const float4*)&As[kk * 128 + ty * 8];
            float4 a1 = *(const float4*)&As[kk * 128 + ty * 8 + 4];
            float4 b0 = *(const float4*)&Bs[kk * 128 + tx * 8];
            float4 b1 = *(const float4*)&Bs[kk * 128 + tx * 8 + 4];
            float ar[8] = {a0.x, a0.y, a0.z, a0.w, a1.x, a1.y, a1.z, a1.w};
            float br[8] = {b0.x, b0.y, b0.z, b0.w, b1.x, b1.y, b1.z, b1.w};
#pragma unroll
            for (int i = 0; i < 8; i++)
#pragma unroll
                for (int j = 0; j < 8; j++)
                    acc[i][j] += ar[i] * br[j];
        }
        __syncthreads();
    }

#pragma unroll
    for (int i = 0; i < 8; i++) {
        const int gm = m0 + ty * 8 + i;
#pragma unroll
        for (int j4 = 0; j4 < 2; j4++) {
            const int gn = n0 + tx * 8 + j4 * 4;
            float4 o;
            o.x = acc[i][j4 * 4 + 0] + bias[gn + 0];
            o.y = acc[i][j4 * 4 + 1] + bias[gn + 1];
            o.z = acc[i][j4 * 4 + 2] + bias[gn + 2];
            o.w = acc[i][j4 * 4 + 3] + bias[gn + 3];
            *(float4*)(out + (size_t)gm * N + gn) = o;
        }
    }
}

// ---------------------------------------------------------------------------
// Fused sigmoid attention.
// Grid: (S/64, NH, B). One CTA = 64 query rows of one (b,h).
// Per key tile of 64: S = Q@K^T * 0.125 -> sigmoid -> att_map (store once) and
// Ps in smem; then O += Ps @ V. K^T and V smem use XOR-swizzled float4 groups.
// Static smem = 3 * 16KB = 48KB exactly.
// ---------------------------------------------------------------------------
template <bool WRITE_MAP>
__global__ void __launch_bounds__(256) attn_k(float* __restrict__ att_map)
{
    __shared__ float Qs[64 * 64];
    __shared__ float KVs[64 * 64];
    __shared__ float Ps[64 * 64];

    const int b = blockIdx.z, h = blockIdx.y, rt = blockIdx.x;
    const int tid = threadIdx.x;
    const int tx = tid & 15, ty = tid >> 4;
    const int row0 = rt * 64;

    const float* qb = g_q + (size_t)(b * Ss + row0) * Hdim + h * DH;
    const float* kb = g_k + (size_t)(b * Ss) * Hdim + h * DH;
    const float* vb = g_v + (size_t)(b * Ss) * Hdim + h * DH;
    float* am = att_map + ((size_t)(b * NH + h) * Ss + row0) * Ss;

    // Load Q tile (row-major, conflict-free)
    for (int i = tid; i < 64 * 64; i += 256) {
        const int r = i >> 6, d = i & 63;
        Qs[r * 64 + d] = qb[(size_t)r * Hdim + d];
    }

    float acc[4][4];
#pragma unroll
    for (int i = 0; i < 4; i++)
#pragma unroll
        for (int j = 0; j < 4; j++) acc[i][j] = 0.0f;

    __syncthreads();

    for (int kt = 0; kt < Ss / 64; kt++) {
        // ---- load K tile transposed (d-major), XOR swizzle on t-groups ----
        {
            const float* kp = kb + (size_t)kt * 64 * Hdim;
            for (int i = tid; i < 64 * 64; i += 256) {
                const int t = i >> 6, d = i & 63;
                const int c = ((((t >> 2) ^ (d & 15)) << 2) | (t & 3));
                KVs[d * 64 + c] = kp[(size_t)t * Hdim + d];
            }
        }
        __syncthreads();

        // ---- S = Q @ K^T ----
        float sac[4][4];
#pragma unroll
        for (int i = 0; i < 4; i++)
#pragma unroll
            for (int j = 0; j < 4; j++) sac[i][j] = 0.0f;

#pragma unroll 4
        for (int d4 = 0; d4 < 16; d4++) {
            float4 qa[4];
#pragma unroll
            for (int i = 0; i < 4; i++)
                qa[i] = *(const float4*)&Qs[(ty * 4 + i) * 64 + d4 * 4];
#pragma unroll
            for (int dd = 0; dd < 4; dd++) {
                const int d = d4 * 4 + dd;
                const float4 kv =
                    *(const float4*)&KVs[d * 64 + ((tx ^ (d & 15)) << 2)];
#pragma unroll
                for (int i = 0; i < 4; i++) {
                    const float qv = ((const float*)&qa[i])[dd];
                    sac[i][0] += qv * kv.x;
                    sac[i][1] += qv * kv.y;
                    sac[i][2] += qv * kv.z;
                    sac[i][3] += qv * kv.w;
                }
            }
        }

        // ---- sigmoid, store att_map (once) + Ps ----
#pragma unroll
        for (int i = 0; i < 4; i++) {
            float4 p;
            p.x = 1.0f / (1.0f + __expf(-0.125f * sac[i][0]));
            p.y = 1.0f / (1.0f + __expf(-0.125f * sac[i][1]));
            p.z = 1.0f / (1.0f + __expf(-0.125f * sac[i][2]));
            p.w = 1.0f / (1.0f + __expf(-0.125f * sac[i][3]));
            *(float4*)&Ps[(ty * 4 + i) * 64 + tx * 4] = p;
            if (WRITE_MAP)
                *(float4*)(am + (size_t)(ty * 4 + i) * Ss + kt * 64 + tx * 4) = p;
        }
        __syncthreads();

        // ---- load V tile (t-major), XOR swizzle on d-groups ----
        {
            const float* vp = vb + (size_t)kt * 64 * Hdim;
            for (int i = tid; i < 64 * 64; i += 256) {
                const int t = i >> 6, d = i & 63;
                const int c = ((((d >> 2) ^ (t & 15)) << 2) | (d & 3));
                KVs[t * 64 + c] = vp[(size_t)t * Hdim + d];
            }
        }
        __syncthreads();

        // ---- O += Ps @ V ----
#pragma unroll 4
        for (int t4 = 0; t4 < 16; t4++) {
            float4 pa[4];
#pragma unroll
            for (int i = 0; i < 4; i++)
                pa[i] = *(const float4*)&Ps[(ty * 4 + i) * 64 + t4 * 4];
#pragma unroll
            for (int tt = 0; tt < 4; tt++) {
                const int t = t4 * 4 + tt;
                const float4 vv =
                    *(const float4*)&KVs[t * 64 + ((tx ^ (t & 15)) << 2)];
#pragma unroll
                for (int i = 0; i < 4; i++) {
                    const float pv = ((const float*)&pa[i])[tt];
                    acc[i][0] += pv * vv.x;
                    acc[i][1] += pv * vv.y;
                    acc[i][2] += pv * vv.z;
                    acc[i][3] += pv * vv.w;
                }
            }
        }
        __syncthreads();
    }

    // ---- write atted rows back to [B*S, H] layout ----
    float* ob = g_o + (size_t)(b * Ss + row0) * Hdim + h * DH;
#pragma unroll
    for (int i = 0; i < 4; i++) {
        float4 o = make_float4(acc[i][0], acc[i][1], acc[i][2], acc[i][3]);
        *(float4*)(ob + (size_t)(ty * 4 + i) * Hdim + tx * 4) = o;
    }
}

// ---------------------------------------------------------------------------
extern "C" void kernel_launch(void* const* d_in, const int* in_sizes, int n_in,
                              void* d_out, int out_size)
{
    (void)in_sizes; (void)n_in;
    const float* v  = (const float*)d_in[0];
    const float* k  = (const float*)d_in[1];
    const float* q  = (const float*)d_in[2];
    const float* Wv = (const float*)d_in[3];
    const float* bv = (const float*)d_in[4];
    const float* Wk = (const float*)d_in[5];
    const float* bk = (const float*)d_in[6];
    const float* Wq = (const float*)d_in[7];
    const float* bq = (const float*)d_in[8];
    const float* Wm = (const float*)d_in[9];
    const float* bm = (const float*)d_in[10];
    float* out = (float*)d_out;

    float *gq, *gk, *gv, *go;
    cudaGetSymbolAddress((void**)&gq, g_q);
    cudaGetSymbolAddress((void**)&gk, g_k);
    cudaGetSymbolAddress((void**)&gv, g_v);
    cudaGetSymbolAddress((void**)&go, g_o);

    dim3 gg(Hdim / 128, MT / 128);  // (8, 32)
    sgemm_bias_k<<<gg, 256>>>(q, Wq, bq, gq);
    sgemm_bias_k<<<gg, 256>>>(k, Wk, bk, gk);
    sgemm_bias_k<<<gg, 256>>>(v, Wv, bv, gv);

    const long long atted_elems = (long long)MT * Hdim;                 // 4,194,304
    const long long map_elems   = (long long)Bb * NH * Ss * Ss;         // 134,217,728
    dim3 ga(Ss / 64, NH, Bb);
    if ((long long)out_size >= atted_elems + map_elems) {
        attn_k<true><<<ga, 256>>>(out + (size_t)atted_elems);
    } else {
        attn_k<false><<<ga, 256>>>(nullptr);
    }

    sgemm_bias_k<<<gg, 256>>>(go, Wm, bm, out);
}

// round 2
// speedup vs baseline: 1.0043x; 1.0043x over previous
#include <cuda_runtime.h>
#include <math.h>

// Problem constants
#define Hdim 1024
#define NH   16
#define DH   64
#define Bb   2
#define Ss   2048
#define MT   (Bb * Ss)   // 4096 rows

// Scratch (no allocations allowed -> __device__ globals), 16 MB each
__device__ float g_q[MT * Hdim];
__device__ float g_k[MT * Hdim];
__device__ float g_v[MT * Hdim];
__device__ float g_o[MT * Hdim];

// ---------------------------------------------------------------------------
// GEMM: out[M,N] = A[M,K] @ W[N,K]^T + bias[N]   (M=4096, N=K=1024)
// 128x128 block tile, BK=8, 256 threads, 8x8 per-thread micro-tile.
// ---------------------------------------------------------------------------
__global__ void __launch_bounds__(256) sgemm_bias_k(
    const float* __restrict__ A, const float* __restrict__ W,
    const float* __restrict__ bias, float* __restrict__ out)
{
    const int K = Hdim, N = Hdim;
    __shared__ float As[8 * 128];
    __shared__ float Bs[8 * 128];

    const int tid = threadIdx.x;
    const int tx = tid & 15, ty = tid >> 4;
    const int m0 = blockIdx.y * 128, n0 = blockIdx.x * 128;

    const int lrow = tid >> 1;
    const int lkg  = (tid & 1) * 4;
    const float* Ap = A + (size_t)(m0 + lrow) * K + lkg;
    const float* Wp = W + (size_t)(n0 + lrow) * K + lkg;

    float acc[8][8];
#pragma unroll
    for (int i = 0; i < 8; i++)
#pragma unroll
        for (int j = 0; j < 8; j++) acc[i][j] = 0.0f;

    for (int k0 = 0; k0 < K; k0 += 8) {
        float4 av = *(const float4*)(Ap + k0);
        float4 wv = *(const float4*)(Wp + k0);
        As[(lkg + 0) * 128 + lrow] = av.x;
        As[(lkg + 1) * 128 + lrow] = av.y;
        As[(lkg + 2) * 128 + lrow] = av.z;
        As[(lkg + 3) * 128 + lrow] = av.w;
        Bs[(lkg + 0) * 128 + lrow] = wv.x;
        Bs[(lkg + 1) * 128 + lrow] = wv.y;
        Bs[(lkg + 2) * 128 + lrow] = wv.z;
        Bs[(lkg + 3) * 128 + lrow] = wv.w;
        __syncthreads();

#pragma unroll
        for (int kk = 0; kk < 8; kk++) {
            float4 a0 = *(const float4*)&As[kk * 128 + ty * 8];
            float4 a1 = *(const float4*)&As[kk * 128 + ty * 8 + 4];
            float4 b0 = *(const float4*)&Bs[kk * 128 + tx * 8];
            float4 b1 = *(const float4*)&Bs[kk * 128 + tx * 8 + 4];
            float ar[8] = {a0.x, a0.y, a0.z, a0.w, a1.x, a1.y, a1.z, a1.w};
            float br[8] = {b0.x, b0.y, b0.z, b0.w, b1.x, b1.y, b1.z, b1.w};
#pragma unroll
            for (int i = 0; i < 8; i++)
#pragma unroll
                for (int j = 0; j < 8; j++)
                    acc[i][j] += ar[i] * br[j];
        }
        __syncthreads();
    }

#pragma unroll
    for (int i = 0; i < 8; i++) {
        const int gm = m0 + ty * 8 + i;
#pragma unroll
        for (int j4 = 0; j4 < 2; j4++) {
            const int gn = n0 + tx * 8 + j4 * 4;
            float4 o;
            o.x = acc[i][j4 * 4 + 0] + bias[gn + 0];
            o.y = acc[i][j4 * 4 + 1] + bias[gn + 1];
            o.z = acc[i][j4 * 4 + 2] + bias[gn + 2];
            o.w = acc[i][j4 * 4 + 3] + bias[gn + 3];
            *(float4*)(out + (size_t)gm * N + gn) = o;
        }
    }
}

// ---------------------------------------------------------------------------
// Fused sigmoid attention.
// Grid: (S/64, NH, B). One CTA = 64 query rows of one (b,h).
// Per key tile of 64: S = Q@K^T * 0.125 -> sigmoid -> att_map (store once) and
// Ps in smem; then O += Ps @ V. K^T and V smem use XOR-swizzled float4 groups.
// Static smem = 3 * 16KB = 48KB exactly.
// ---------------------------------------------------------------------------
template <bool WRITE_MAP>
__global__ void __launch_bounds__(256) attn_k(float* __restrict__ att_map)
{
    __shared__ float Qs[64 * 64];
    __shared__ float KVs[64 * 64];
    __shared__ float Ps[64 * 64];

    const int b = blockIdx.z, h = blockIdx.y, rt = blockIdx.x;
    const int tid = threadIdx.x;
    const int tx = tid & 15, ty = tid >> 4;
    const int row0 = rt * 64;

    const float* qb = g_q + (size_t)(b * Ss + row0) * Hdim + h * DH;
    const float* kb = g_k + (size_t)(b * Ss) * Hdim + h * DH;
    const float* vb = g_v + (size_t)(b * Ss) * Hdim + h * DH;
    float* am = att_map + ((size_t)(b * NH + h) * Ss + row0) * Ss;

    // Load Q tile (row-major, conflict-free)
    for (int i = tid; i < 64 * 64; i += 256) {
        const int r = i >> 6, d = i & 63;
        Qs[r * 64 + d] = qb[(size_t)r * Hdim + d];
    }

    float acc[4][4];
#pragma unroll
    for (int i = 0; i < 4; i++)
#pragma unroll
        for (int j = 0; j < 4; j++) acc[i][j] = 0.0f;

    __syncthreads();

    for (int kt = 0; kt < Ss / 64; kt++) {
        // ---- load K tile transposed (d-major), XOR swizzle on t-groups ----
        {
            const float* kp = kb + (size_t)kt * 64 * Hdim;
            for (int i = tid; i < 64 * 64; i += 256) {
                const int t = i >> 6, d = i & 63;
                const int c = ((((t >> 2) ^ (d & 15)) << 2) | (t & 3));
                KVs[d * 64 + c] = kp[(size_t)t * Hdim + d];
            }
        }
        __syncthreads();

        // ---- S = Q @ K^T ----
        float sac[4][4];
#pragma unroll
        for (int i = 0; i < 4; i++)
#pragma unroll
            for (int j = 0; j < 4; j++) sac[i][j] = 0.0f;

#pragma unroll 4
        for (int d4 = 0; d4 < 16; d4++) {
            float4 qa[4];
#pragma unroll
            for (int i = 0; i < 4; i++)
                qa[i] = *(const float4*)&Qs[(ty * 4 + i) * 64 + d4 * 4];
#pragma unroll
            for (int dd = 0; dd < 4; dd++) {
                const int d = d4 * 4 + dd;
                const float4 kv =
                    *(const float4*)&KVs[d * 64 + ((tx ^ (d & 15)) << 2)];
#pragma unroll
                for (int i = 0; i < 4; i++) {
                    const float qv = ((const float*)&qa[i])[dd];
                    sac[i][0] += qv * kv.x;
                    sac[i][1] += qv * kv.y;
                    sac[i][2] += qv * kv.z;
                    sac[i][3] += qv * kv.w;
                }
            }
        }

        // ---- sigmoid, store att_map (once) + Ps ----
#pragma unroll
        for (int i = 0; i < 4; i++) {
            float4 p;
            p.x = 1.0f / (1.0f + __expf(-0.125f * sac[i][0]));
            p.y = 1.0f / (1.0f + __expf(-0.125f * sac[i][1]));
            p.z = 1.0f / (1.0f + __expf(-0.125f * sac[i][2]));
            p.w = 1.0f / (1.0f + __expf(-0.125f * sac[i][3]));
            *(float4*)&Ps[(ty * 4 + i) * 64 + tx * 4] = p;
            if (WRITE_MAP)
                *(float4*)(am + (size_t)(ty * 4 + i) * Ss + kt * 64 + tx * 4) = p;
        }
        __syncthreads();

        // ---- load V tile (t-major), XOR swizzle on d-groups ----
        {
            const float* vp = vb + (size_t)kt * 64 * Hdim;
            for (int i = tid; i < 64 * 64; i += 256) {
                const int t = i >> 6, d = i & 63;
                const int c = ((((d >> 2) ^ (t & 15)) << 2) | (d & 3));
                KVs[t * 64 + c] = vp[(size_t)t * Hdim + d];
            }
        }
        __syncthreads();

        // ---- O += Ps @ V ----
#pragma unroll 4
        for (int t4 = 0; t4 < 16; t4++) {
            float4 pa[4];
#pragma unroll
            for (int i = 0; i < 4; i++)
                pa[i] = *(const float4*)&Ps[(ty * 4 + i) * 64 + t4 * 4];
#pragma unroll
            for (int tt = 0; tt < 4; tt++) {
                const int t = t4 * 4 + tt;
                const float4 vv =
                    *(const float4*)&KVs[t * 64 + ((tx ^ (t & 15)) << 2)];
#pragma unroll
                for (int i = 0; i < 4; i++) {
                    const float pv = ((const float*)&pa[i])[tt];
                    acc[i][0] += pv * vv.x;
                    acc[i][1] += pv * vv.y;
                    acc[i][2] += pv * vv.z;
                    acc[i][3] += pv * vv.w;
                }
            }
        }
        __syncthreads();
    }

    // ---- write atted rows back to [B*S, H] layout ----
    float* ob = g_o + (size_t)(b * Ss + row0) * Hdim + h * DH;
#pragma unroll
    for (int i = 0; i < 4; i++) {
        float4 o = make_float4(acc[i][0], acc[i][1], acc[i][2], acc[i][3]);
        *(float4*)(ob + (size_t)(ty * 4 + i) * Hdim + tx * 4) = o;
    }
}

// ---------------------------------------------------------------------------
extern "C" void kernel_launch(void* const* d_in, const int* in_sizes, int n_in,
                              void* d_out, int out_size)
{
    (void)in_sizes; (void)n_in;
    const float* v  = (const float*)d_in[0];
    const float* k  = (const float*)d_in[1];
    const float* q  = (const float*)d_in[2];
    const float* Wv = (const float*)d_in[3];
    const float* bv = (const float*)d_in[4];
    const float* Wk = (const float*)d_in[5];
    const float* bk = (const float*)d_in[6];
    const float* Wq = (const float*)d_in[7];
    const float* bq = (const float*)d_in[8];
    const float* Wm = (const float*)d_in[9];
    const float* bm = (const float*)d_in[10];
    float* out = (float*)d_out;

    float *gq, *gk, *gv, *go;
    cudaGetSymbolAddress((void**)&gq, g_q);
    cudaGetSymbolAddress((void**)&gk, g_k);
    cudaGetSymbolAddress((void**)&gv, g_v);
    cudaGetSymbolAddress((void**)&go, g_o);

    dim3 gg(Hdim / 128, MT / 128);  // (8, 32)
    sgemm_bias_k<<<gg, 256>>>(q, Wq, bq, gq);
    sgemm_bias_k<<<gg, 256>>>(k, Wk, bk, gk);
    sgemm_bias_k<<<gg, 256>>>(v, Wv, bv, gv);

    const long long atted_elems = (long long)MT * Hdim;                 // 4,194,304
    const long long map_elems   = (long long)Bb * NH * Ss * Ss;         // 134,217,728
    dim3 ga(Ss / 64, NH, Bb);
    if ((long long)out_size >= atted_elems + map_elems) {
        attn_k<true><<<ga, 256>>>(out + (size_t)atted_elems);
    } else {
        attn_k<false><<<ga, 256>>>(nullptr);
    }

    sgemm_bias_k<<<gg, 256>>>(go, Wm, bm, out);
}

// round 3
// speedup vs baseline: 1.0048x; 1.0004x over previous
#include <cuda_runtime.h>
#include <math.h>

// Problem constants
#define Hdim 1024
#define NH   16
#define DH   64
#define Bb   2
#define Ss   2048
#define MT   (Bb * Ss)   // 4096 rows

// Scratch (no allocations allowed -> __device__ globals), 16 MB each
__device__ float g_q[MT * Hdim];
__device__ float g_k[MT * Hdim];
__device__ float g_v[MT * Hdim];
__device__ float g_o[MT * Hdim];

// ---------------------------------------------------------------------------
// GEMM: out[M,N] = A[M,K] @ W[N,K]^T + bias[N]   (M=4096, N=K=1024)
// 128x128 block tile, BK=8, 256 threads, 8x8 per-thread micro-tile.
// ---------------------------------------------------------------------------
__global__ void __launch_bounds__(256) sgemm_bias_k(
    const float* __restrict__ A, const float* __restrict__ W,
    const float* __restrict__ bias, float* __restrict__ out)
{
    const int K = Hdim, N = Hdim;
    __shared__ float As[8 * 128];
    __shared__ float Bs[8 * 128];

    const int tid = threadIdx.x;
    const int tx = tid & 15, ty = tid >> 4;
    const int m0 = blockIdx.y * 128, n0 = blockIdx.x * 128;

    const int lrow = tid >> 1;
    const int lkg  = (tid & 1) * 4;
    const float* Ap = A + (size_t)(m0 + lrow) * K + lkg;
    const float* Wp = W + (size_t)(n0 + lrow) * K + lkg;

    float acc[8][8];
#pragma unroll
    for (int i = 0; i < 8; i++)
#pragma unroll
        for (int j = 0; j < 8; j++) acc[i][j] = 0.0f;

    for (int k0 = 0; k0 < K; k0 += 8) {
        float4 av = *(const float4*)(Ap + k0);
        float4 wv = *(const float4*)(Wp + k0);
        As[(lkg + 0) * 128 + lrow] = av.x;
        As[(lkg + 1) * 128 + lrow] = av.y;
        As[(lkg + 2) * 128 + lrow] = av.z;
        As[(lkg + 3) * 128 + lrow] = av.w;
        Bs[(lkg + 0) * 128 + lrow] = wv.x;
        Bs[(lkg + 1) * 128 + lrow] = wv.y;
        Bs[(lkg + 2) * 128 + lrow] = wv.z;
        Bs[(lkg + 3) * 128 + lrow] = wv.w;
        __syncthreads();

#pragma unroll
        for (int kk = 0; kk < 8; kk++) {
            float4 a0 = *(const float4*)&As[kk * 128 + ty * 8];
            float4 a1 = *(const float4*)&As[kk * 128 + ty * 8 + 4];
            float4 b0 = *(const float4*)&Bs[kk * 128 + tx * 8];
            float4 b1 = *(const float4*)&Bs[kk * 128 + tx * 8 + 4];
            float ar[8] = {a0.x, a0.y, a0.z, a0.w, a1.x, a1.y, a1.z, a1.w};
            float br[8] = {b0.x, b0.y, b0.z, b0.w, b1.x, b1.y, b1.z, b1.w};
#pragma unroll
            for (int i = 0; i < 8; i++)
#pragma unroll
                for (int j = 0; j < 8; j++)
                    acc[i][j] += ar[i] * br[j];
        }
        __syncthreads();
    }

#pragma unroll
    for (int i = 0; i < 8; i++) {
        const int gm = m0 + ty * 8 + i;
#pragma unroll
        for (int j4 = 0; j4 < 2; j4++) {
            const int gn = n0 + tx * 8 + j4 * 4;
            float4 o;
            o.x = acc[i][j4 * 4 + 0] + bias[gn + 0];
            o.y = acc[i][j4 * 4 + 1] + bias[gn + 1];
            o.z = acc[i][j4 * 4 + 2] + bias[gn + 2];
            o.w = acc[i][j4 * 4 + 3] + bias[gn + 3];
            *(float4*)(out + (size_t)gm * N + gn) = o;
        }
    }
}

// ---------------------------------------------------------------------------
// Fused sigmoid attention.
// Grid: (S/64, NH, B). One CTA = 64 query rows of one (b,h).
// Per key tile of 64: S = Q@K^T * 0.125 -> sigmoid -> att_map (store once) and
// Ps in smem; then O += Ps @ V. K^T and V smem use XOR-swizzled float4 groups.
// Static smem = 3 * 16KB = 48KB exactly.
// ---------------------------------------------------------------------------
template <bool WRITE_MAP>
__global__ void __launch_bounds__(256) attn_k(float* __restrict__ att_map)
{
    __shared__ float Qs[64 * 64];
    __shared__ float KVs[64 * 64];
    __shared__ float Ps[64 * 64];

    const int b = blockIdx.z, h = blockIdx.y, rt = blockIdx.x;
    const int tid = threadIdx.x;
    const int tx = tid & 15, ty = tid >> 4;
    const int row0 = rt * 64;

    const float* qb = g_q + (size_t)(b * Ss + row0) * Hdim + h * DH;
    const float* kb = g_k + (size_t)(b * Ss) * Hdim + h * DH;
    const float* vb = g_v + (size_t)(b * Ss) * Hdim + h * DH;
    float* am = att_map + ((size_t)(b * NH + h) * Ss + row0) * Ss;

    // Load Q tile (row-major, conflict-free)
    for (int i = tid; i < 64 * 64; i += 256) {
        const int r = i >> 6, d = i & 63;
        Qs[r * 64 + d] = qb[(size_t)r * Hdim + d];
    }

    float acc[4][4];
#pragma unroll
    for (int i = 0; i < 4; i++)
#pragma unroll
        for (int j = 0; j < 4; j++) acc[i][j] = 0.0f;

    __syncthreads();

    for (int kt = 0; kt < Ss / 64; kt++) {
        // ---- load K tile transposed (d-major), XOR swizzle on t-groups ----
        {
            const float* kp = kb + (size_t)kt * 64 * Hdim;
            for (int i = tid; i < 64 * 64; i += 256) {
                const int t = i >> 6, d = i & 63;
                const int c = ((((t >> 2) ^ (d & 15)) << 2) | (t & 3));
                KVs[d * 64 + c] = kp[(size_t)t * Hdim + d];
            }
        }
        __syncthreads();

        // ---- S = Q @ K^T ----
        float sac[4][4];
#pragma unroll
        for (int i = 0; i < 4; i++)
#pragma unroll
            for (int j = 0; j < 4; j++) sac[i][j] = 0.0f;

#pragma unroll 4
        for (int d4 = 0; d4 < 16; d4++) {
            float4 qa[4];
#pragma unroll
            for (int i = 0; i < 4; i++)
                qa[i] = *(const float4*)&Qs[(ty * 4 + i) * 64 + d4 * 4];
#pragma unroll
            for (int dd = 0; dd < 4; dd++) {
                const int d = d4 * 4 + dd;
                const float4 kv =
                    *(const float4*)&KVs[d * 64 + ((tx ^ (d & 15)) << 2)];
#pragma unroll
                for (int i = 0; i < 4; i++) {
                    const float qv = ((const float*)&qa[i])[dd];
                    sac[i][0] += qv * kv.x;
                    sac[i][1] += qv * kv.y;
                    sac[i][2] += qv * kv.z;
                    sac[i][3] += qv * kv.w;
                }
            }
        }

        // ---- sigmoid, store att_map (once) + Ps ----
#pragma unroll
        for (int i = 0; i < 4; i++) {
            float4 p;
            p.x = 1.0f / (1.0f + __expf(-0.125f * sac[i][0]));
            p.y = 1.0f / (1.0f + __expf(-0.125f * sac[i][1]));
            p.z = 1.0f / (1.0f + __expf(-0.125f * sac[i][2]));
            p.w = 1.0f / (1.0f + __expf(-0.125f * sac[i][3]));
            *(float4*)&Ps[(ty * 4 + i) * 64 + tx * 4] = p;
            if (WRITE_MAP)
                *(float4*)(am + (size_t)(ty * 4 + i) * Ss + kt * 64 + tx * 4) = p;
        }
        __syncthreads();

        // ---- load V tile (t-major), XOR swizzle on d-groups ----
        {
            const float* vp = vb + (size_t)kt * 64 * Hdim;
            for (int i = tid; i < 64 * 64; i += 256) {
                const int t = i >> 6, d = i & 63;
                const int c = ((((d >> 2) ^ (t & 15)) << 2) | (d & 3));
                KVs[t * 64 + c] = vp[(size_t)t * Hdim + d];
            }
        }
        __syncthreads();

        // ---- O += Ps @ V ----
#pragma unroll 4
        for (int t4 = 0; t4 < 16; t4++) {
            float4 pa[4];
#pragma unroll
            for (int i = 0; i < 4; i++)
                pa[i] = *(const float4*)&Ps[(ty * 4 + i) * 64 + t4 * 4];
#pragma unroll
            for (int tt = 0; tt < 4; tt++) {
                const int t = t4 * 4 + tt;
                const float4 vv =
                    *(const float4*)&KVs[t * 64 + ((tx ^ (t & 15)) << 2)];
#pragma unroll
                for (int i = 0; i < 4; i++) {
                    const float pv = ((const float*)&pa[i])[tt];
                    acc[i][0] += pv * vv.x;
                    acc[i][1] += pv * vv.y;
                    acc[i][2] += pv * vv.z;
                    acc[i][3] += pv * vv.w;
                }
            }
        }
        __syncthreads();
    }

    // ---- write atted rows back to [B*S, H] layout ----
    float* ob = g_o + (size_t)(b * Ss + row0) * Hdim + h * DH;
#pragma unroll
    for (int i = 0; i < 4; i++) {
        float4 o = make_float4(acc[i][0], acc[i][1], acc[i][2], acc[i][3]);
        *(float4*)(ob + (size_t)(ty * 4 + i) * Hdim + tx * 4) = o;
    }
}

// ---------------------------------------------------------------------------
extern "C" void kernel_launch(void* const* d_in, const int* in_sizes, int n_in,
                              void* d_out, int out_size)
{
    (void)in_sizes; (void)n_in;
    const float* v  = (const float*)d_in[0];
    const float* k  = (const float*)d_in[1];
    const float* q  = (const float*)d_in[2];
    const float* Wv = (const float*)d_in[3];
    const float* bv = (const float*)d_in[4];
    const float* Wk = (const float*)d_in[5];
    const float* bk = (const float*)d_in[6];
    const float* Wq = (const float*)d_in[7];
    const float* bq = (const float*)d_in[8];
    const float* Wm = (const float*)d_in[9];
    const float* bm = (const float*)d_in[10];
    float* out = (float*)d_out;

    float *gq, *gk, *gv, *go;
    cudaGetSymbolAddress((void**)&gq, g_q);
    cudaGetSymbolAddress((void**)&gk, g_k);
    cudaGetSymbolAddress((void**)&gv, g_v);
    cudaGetSymbolAddress((void**)&go, g_o);

    dim3 gg(Hdim / 128, MT / 128);  // (8, 32)
    sgemm_bias_k<<<gg, 256>>>(q, Wq, bq, gq);
    sgemm_bias_k<<<gg, 256>>>(k, Wk, bk, gk);
    sgemm_bias_k<<<gg, 256>>>(v, Wv, bv, gv);

    const long long atted_elems = (long long)MT * Hdim;                 // 4,194,304
    const long long map_elems   = (long long)Bb * NH * Ss * Ss;         // 134,217,728
    dim3 ga(Ss / 64, NH, Bb);
    if ((long long)out_size >= atted_elems + map_elems) {
        attn_k<true><<<ga, 256>>>(out + (size_t)atted_elems);
    } else {
        attn_k<false><<<ga, 256>>>(nullptr);
    }

    sgemm_bias_k<<<gg, 256>>>(go, Wm, bm, out);
}

// round 4
// speedup vs baseline: 1.0064x; 1.0017x over previous
#include <cuda_runtime.h>
#include <math.h>

// Problem constants
#define Hdim 1024
#define NH   16
#define DH   64
#define Bb   2
#define Ss   2048
#define MT   (Bb * Ss)   // 4096 rows

// Scratch (no allocations allowed -> __device__ globals), 16 MB each
__device__ float g_q[MT * Hdim];
__device__ float g_k[MT * Hdim];
__device__ float g_v[MT * Hdim];
__device__ float g_o[MT * Hdim];

// ---------------------------------------------------------------------------
// GEMM: out[M,N] = A[M,K] @ W[N,K]^T + bias[N]   (M=4096, N=K=1024)
// 128x128 block tile, BK=8, 256 threads, 8x8 per-thread micro-tile.
// ---------------------------------------------------------------------------
__global__ void __launch_bounds__(256) sgemm_bias_k(
    const float* __restrict__ A, const float* __restrict__ W,
    const float* __restrict__ bias, float* __restrict__ out)
{
    const int K = Hdim, N = Hdim;
    __shared__ float As[8 * 128];
    __shared__ float Bs[8 * 128];

    const int tid = threadIdx.x;
    const int tx = tid & 15, ty = tid >> 4;
    const int m0 = blockIdx.y * 128, n0 = blockIdx.x * 128;

    const int lrow = tid >> 1;
    const int lkg  = (tid & 1) * 4;
    const float* Ap = A + (size_t)(m0 + lrow) * K + lkg;
    const float* Wp = W + (size_t)(n0 + lrow) * K + lkg;

    float acc[8][8];
#pragma unroll
    for (int i = 0; i < 8; i++)
#pragma unroll
        for (int j = 0; j < 8; j++) acc[i][j] = 0.0f;

    for (int k0 = 0; k0 < K; k0 += 8) {
        float4 av = *(const float4*)(Ap + k0);
        float4 wv = *(const float4*)(Wp + k0);
        As[(lkg + 0) * 128 + lrow] = av.x;
        As[(lkg + 1) * 128 + lrow] = av.y;
        As[(lkg + 2) * 128 + lrow] = av.z;
        As[(lkg + 3) * 128 + lrow] = av.w;
        Bs[(lkg + 0) * 128 + lrow] = wv.x;
        Bs[(lkg + 1) * 128 + lrow] = wv.y;
        Bs[(lkg + 2) * 128 + lrow] = wv.z;
        Bs[(lkg + 3) * 128 + lrow] = wv.w;
        __syncthreads();

#pragma unroll
        for (int kk = 0; kk < 8; kk++) {
            float4 a0 = *(const float4*)&As[kk * 128 + ty * 8];
            float4 a1 = *(const float4*)&As[kk * 128 + ty * 8 + 4];
            float4 b0 = *(const float4*)&Bs[kk * 128 + tx * 8];
            float4 b1 = *(const float4*)&Bs[kk * 128 + tx * 8 + 4];
            float ar[8] = {a0.x, a0.y, a0.z, a0.w, a1.x, a1.y, a1.z, a1.w};
            float br[8] = {b0.x, b0.y, b0.z, b0.w, b1.x, b1.y, b1.z, b1.w};
#pragma unroll
            for (int i = 0; i < 8; i++)
#pragma unroll
                for (int j = 0; j < 8; j++)
                    acc[i][j] += ar[i] * br[j];
        }
        __syncthreads();
    }

#pragma unroll
    for (int i = 0; i < 8; i++) {
        const int gm = m0 + ty * 8 + i;
#pragma unroll
        for (int j4 = 0; j4 < 2; j4++) {
            const int gn = n0 + tx * 8 + j4 * 4;
            float4 o;
            o.x = acc[i][j4 * 4 + 0] + bias[gn + 0];
            o.y = acc[i][j4 * 4 + 1] + bias[gn + 1];
            o.z = acc[i][j4 * 4 + 2] + bias[gn + 2];
            o.w = acc[i][j4 * 4 + 3] + bias[gn + 3];
            *(float4*)(out + (size_t)gm * N + gn) = o;
        }
    }
}

// ---------------------------------------------------------------------------
// Fused sigmoid attention.
// Grid: (S/64, NH, B). One CTA = 64 query rows of one (b,h).
// Per key tile of 64: S = Q@K^T * 0.125 -> sigmoid -> att_map (store once) and
// Ps in smem; then O += Ps @ V. K^T and V smem use XOR-swizzled float4 groups.
// Static smem = 3 * 16KB = 48KB exactly.
// ---------------------------------------------------------------------------
template <bool WRITE_MAP>
__global__ void __launch_bounds__(256) attn_k(float* __restrict__ att_map)
{
    __shared__ float Qs[64 * 64];
    __shared__ float KVs[64 * 64];
    __shared__ float Ps[64 * 64];

    const int b = blockIdx.z, h = blockIdx.y, rt = blockIdx.x;
    const int tid = threadIdx.x;
    const int tx = tid & 15, ty = tid >> 4;
    const int row0 = rt * 64;

    const float* qb = g_q + (size_t)(b * Ss + row0) * Hdim + h * DH;
    const float* kb = g_k + (size_t)(b * Ss) * Hdim + h * DH;
    const float* vb = g_v + (size_t)(b * Ss) * Hdim + h * DH;
    float* am = att_map + ((size_t)(b * NH + h) * Ss + row0) * Ss;

    // Load Q tile (row-major, conflict-free)
    for (int i = tid; i < 64 * 64; i += 256) {
        const int r = i >> 6, d = i & 63;
        Qs[r * 64 + d] = qb[(size_t)r * Hdim + d];
    }

    float acc[4][4];
#pragma unroll
    for (int i = 0; i < 4; i++)
#pragma unroll
        for (int j = 0; j < 4; j++) acc[i][j] = 0.0f;

    __syncthreads();

    for (int kt = 0; kt < Ss / 64; kt++) {
        // ---- load K tile transposed (d-major), XOR swizzle on t-groups ----
        {
            const float* kp = kb + (size_t)kt * 64 * Hdim;
            for (int i = tid; i < 64 * 64; i += 256) {
                const int t = i >> 6, d = i & 63;
                const int c = ((((t >> 2) ^ (d & 15)) << 2) | (t & 3));
                KVs[d * 64 + c] = kp[(size_t)t * Hdim + d];
            }
        }
        __syncthreads();

        // ---- S = Q @ K^T ----
        float sac[4][4];
#pragma unroll
        for (int i = 0; i < 4; i++)
#pragma unroll
            for (int j = 0; j < 4; j++) sac[i][j] = 0.0f;

#pragma unroll 4
        for (int d4 = 0; d4 < 16; d4++) {
            float4 qa[4];
#pragma unroll
            for (int i = 0; i < 4; i++)
                qa[i] = *(const float4*)&Qs[(ty * 4 + i) * 64 + d4 * 4];
#pragma unroll
            for (int dd = 0; dd < 4; dd++) {
                const int d = d4 * 4 + dd;
                const float4 kv =
                    *(const float4*)&KVs[d * 64 + ((tx ^ (d & 15)) << 2)];
#pragma unroll
                for (int i = 0; i < 4; i++) {
                    const float qv = ((const float*)&qa[i])[dd];
                    sac[i][0] += qv * kv.x;
                    sac[i][1] += qv * kv.y;
                    sac[i][2] += qv * kv.z;
                    sac[i][3] += qv * kv.w;
                }
            }
        }

        // ---- sigmoid, store att_map (once) + Ps ----
#pragma unroll
        for (int i = 0; i < 4; i++) {
            float4 p;
            p.x = 1.0f / (1.0f + __expf(-0.125f * sac[i][0]));
            p.y = 1.0f / (1.0f + __expf(-0.125f * sac[i][1]));
            p.z = 1.0f / (1.0f + __expf(-0.125f * sac[i][2]));
            p.w = 1.0f / (1.0f + __expf(-0.125f * sac[i][3]));
            *(float4*)&Ps[(ty * 4 + i) * 64 + tx * 4] = p;
            if (WRITE_MAP)
                *(float4*)(am + (size_t)(ty * 4 + i) * Ss + kt * 64 + tx * 4) = p;
        }
        __syncthreads();

        // ---- load V tile (t-major), XOR swizzle on d-groups ----
        {
            const float* vp = vb + (size_t)kt * 64 * Hdim;
            for (int i = tid; i < 64 * 64; i += 256) {
                const int t = i >> 6, d = i & 63;
                const int c = ((((d >> 2) ^ (t & 15)) << 2) | (d & 3));
                KVs[t * 64 + c] = vp[(size_t)t * Hdim + d];
            }
        }
        __syncthreads();

        // ---- O += Ps @ V ----
#pragma unroll 4
        for (int t4 = 0; t4 < 16; t4++) {
            float4 pa[4];
#pragma unroll
            for (int i = 0; i < 4; i++)
                pa[i] = *(const float4*)&Ps[(ty * 4 + i) * 64 + t4 * 4];
#pragma unroll
            for (int tt = 0; tt < 4; tt++) {
                const int t = t4 * 4 + tt;
                const float4 vv =
                    *(const float4*)&KVs[t * 64 + ((tx ^ (t & 15)) << 2)];
#pragma unroll
                for (int i = 0; i < 4; i++) {
                    const float pv = ((const float*)&pa[i])[tt];
                    acc[i][0] += pv * vv.x;
                    acc[i][1] += pv * vv.y;
                    acc[i][2] += pv * vv.z;
                    acc[i][3] += pv * vv.w;
                }
            }
        }
        __syncthreads();
    }

    // ---- write atted rows back to [B*S, H] layout ----
    float* ob = g_o + (size_t)(b * Ss + row0) * Hdim + h * DH;
#pragma unroll
    for (int i = 0; i < 4; i++) {
        float4 o = make_float4(acc[i][0], acc[i][1], acc[i][2], acc[i][3]);
        *(float4*)(ob + (size_t)(ty * 4 + i) * Hdim + tx * 4) = o;
    }
}

// ---------------------------------------------------------------------------
extern "C" void kernel_launch(void* const* d_in, const int* in_sizes, int n_in,
                              void* d_out, int out_size)
{
    (void)in_sizes; (void)n_in;
    const float* v  = (const float*)d_in[0];
    const float* k  = (const float*)d_in[1];
    const float* q  = (const float*)d_in[2];
    const float* Wv = (const float*)d_in[3];
    const float* bv = (const float*)d_in[4];
    const float* Wk = (const float*)d_in[5];
    const float* bk = (const float*)d_in[6];
    const float* Wq = (const float*)d_in[7];
    const float* bq = (const float*)d_in[8];
    const float* Wm = (const float*)d_in[9];
    const float* bm = (const float*)d_in[10];
    float* out = (float*)d_out;

    float *gq, *gk, *gv, *go;
    cudaGetSymbolAddress((void**)&gq, g_q);
    cudaGetSymbolAddress((void**)&gk, g_k);
    cudaGetSymbolAddress((void**)&gv, g_v);
    cudaGetSymbolAddress((void**)&go, g_o);

    dim3 gg(Hdim / 128, MT / 128);  // (8, 32)
    sgemm_bias_k<<<gg, 256>>>(q, Wq, bq, gq);
    sgemm_bias_k<<<gg, 256>>>(k, Wk, bk, gk);
    sgemm_bias_k<<<gg, 256>>>(v, Wv, bv, gv);

    const long long atted_elems = (long long)MT * Hdim;                 // 4,194,304
    const long long map_elems   = (long long)Bb * NH * Ss * Ss;         // 134,217,728
    dim3 ga(Ss / 64, NH, Bb);
    if ((long long)out_size >= atted_elems + map_elems) {
        attn_k<true><<<ga, 256>>>(out + (size_t)atted_elems);
    } else {
        attn_k<false><<<ga, 256>>>(nullptr);
    }

    sgemm_bias_k<<<gg, 256>>>(go, Wm, bm, out);
}

// round 6
// speedup vs baseline: 2.6667x; 2.6497x over previous
#include <cuda_runtime.h>
#include <cstdint>
#include <math.h>

#define Hdim 1024
#define NH   16
#define DH   64
#define Bb   2
#define Ss   2048
#define MT   (Bb * Ss)

// Scratch (no allocs allowed)
__device__ float g_q[MT * Hdim];
__device__ float g_k[MT * Hdim];
__device__ float g_v[MT * Hdim];
__device__ float g_o[MT * Hdim];

// ======================= helpers =======================
__device__ __forceinline__ uint32_t s2u(const void* p) {
    uint32_t a;
    asm("{ .reg .u64 t; cvta.to.shared.u64 t, %1; cvt.u32.u64 %0, t; }"
        : "=r"(a) : "l"(p));
    return a;
}
// round-to-nearest tf32 (bit pattern in a float reg)
__device__ __forceinline__ float tf32r(float x) {
    uint32_t u;
    asm("cvt.rna.tf32.f32 %0, %1;" : "=r"(u) : "f"(x));
    return __uint_as_float(u);
}
__device__ __forceinline__ uint32_t tf32u(float x) {
    uint32_t u;
    asm("cvt.rna.tf32.f32 %0, %1;" : "=r"(u) : "f"(x));
    return u;
}

__device__ __forceinline__ void mma8(float* c, const uint32_t* a, const uint32_t* b) {
    asm volatile(
        "mma.sync.aligned.m16n8k8.row.col.f32.tf32.tf32.f32 "
        "{%0,%1,%2,%3}, {%4,%5,%6,%7}, {%8,%9}, {%0,%1,%2,%3};\n"
        : "+f"(c[0]), "+f"(c[1]), "+f"(c[2]), "+f"(c[3])
        : "r"(a[0]), "r"(a[1]), "r"(a[2]), "r"(a[3]), "r"(b[0]), "r"(b[1]));
}

__device__ __forceinline__ void cpa16(uint32_t dst, const void* src) {
    asm volatile("cp.async.cg.shared.global [%0], [%1], 16;" :: "r"(dst), "l"(src));
}
#define CPCOMMIT() asm volatile("cp.async.commit_group;" ::: "memory")
#define CPWAIT0()  asm volatile("cp.async.wait_group 0;" ::: "memory")

__device__ __forceinline__ float sigm(float x) {
    return 1.0f / (1.0f + __expf(-0.125f * x));
}

// ======================= projection GEMM =======================
// out[M,N] = A[M,K] @ W[N,K]^T + bias.  CTA 128x128, BK=32, 256 thr.
#define GP 36

__global__ void __launch_bounds__(256) gemm_mma(
    const float* __restrict__ A, const float* __restrict__ W,
    const float* __restrict__ bias, float* __restrict__ out)
{
    __shared__ float As[128 * GP];
    __shared__ float Bs[128 * GP];
    const int tid = threadIdx.x, wid = tid >> 5, lane = tid & 31;
    const int qr = lane >> 2, qk = lane & 3;
    const int wr = (wid >> 1) * 32, wc = (wid & 1) * 64;
    const int m0 = blockIdx.y * 128, n0 = blockIdx.x * 128;

    float c[2][8][4];
#pragma unroll
    for (int mi = 0; mi < 2; mi++)
#pragma unroll
        for (int ni = 0; ni < 8; ni++)
#pragma unroll
            for (int j = 0; j < 4; j++) c[mi][ni][j] = 0.0f;

    float4 arg[4], wrg[4];
    const int lr = tid >> 3, lc4 = (tid & 7) * 4;

    auto ldchunk = [&](int kc) {
#pragma unroll
        for (int p = 0; p < 4; p++) {
            int r = lr + p * 32;
            arg[p] = *(const float4*)(A + (size_t)(m0 + r) * Hdim + kc * 32 + lc4);
            wrg[p] = *(const float4*)(W + (size_t)(n0 + r) * Hdim + kc * 32 + lc4);
        }
    };
    auto stchunk = [&]() {
#pragma unroll
        for (int p = 0; p < 4; p++) {
            int r = lr + p * 32;
            float4 a = arg[p], w = wrg[p];
            a.x = tf32r(a.x); a.y = tf32r(a.y); a.z = tf32r(a.z); a.w = tf32r(a.w);
            w.x = tf32r(w.x); w.y = tf32r(w.y); w.z = tf32r(w.z); w.w = tf32r(w.w);
            *(float4*)&As[r * GP + lc4] = a;
            *(float4*)&Bs[r * GP + lc4] = w;
        }
    };

    ldchunk(0);
    for (int kc = 0; kc < 32; kc++) {
        stchunk();
        __syncthreads();
        if (kc < 31) ldchunk(kc + 1);
#pragma unroll
        for (int ks = 0; ks < 4; ks++) {
            uint32_t af[2][4], bf[8][2];
#pragma unroll
            for (int mi = 0; mi < 2; mi++) {
                const float* ap = &As[(wr + 16 * mi + qr) * GP + 8 * ks + qk];
                af[mi][0] = __float_as_uint(ap[0]);
                af[mi][1] = __float_as_uint(ap[8 * GP]);
                af[mi][2] = __float_as_uint(ap[4]);
                af[mi][3] = __float_as_uint(ap[8 * GP + 4]);
            }
#pragma unroll
            for (int ni = 0; ni < 8; ni++) {
                const float* bp = &Bs[(wc + 8 * ni + qr) * GP + 8 * ks + qk];
                bf[ni][0] = __float_as_uint(bp[0]);
                bf[ni][1] = __float_as_uint(bp[4]);
            }
#pragma unroll
            for (int mi = 0; mi < 2; mi++)
#pragma unroll
                for (int ni = 0; ni < 8; ni++)
                    mma8(c[mi][ni], af[mi], bf[ni]);
        }
        __syncthreads();
    }

#pragma unroll
    for (int mi = 0; mi < 2; mi++) {
        const int row = m0 + wr + 16 * mi + qr;
#pragma unroll
        for (int ni = 0; ni < 8; ni++) {
            const int col = n0 + wc + 8 * ni + 2 * qk;
            const float b0 = bias[col], b1 = bias[col + 1];
            *(float2*)(out + (size_t)row * Hdim + col) =
                make_float2(c[mi][ni][0] + b0, c[mi][ni][1] + b1);
            *(float2*)(out + (size_t)(row + 8) * Hdim + col) =
                make_float2(c[mi][ni][2] + b0, c[mi][ni][3] + b1);
        }
    }
}

// ======================= fused sigmoid attention =======================
// Grid (16, NH, Bb), 256 thr. CTA: 128 q-rows x 2048 keys (16 tiles of 128).
// S = Q@K^T (MMA, warps 4x2) -> sigmoid -> att_map + P smem -> O += P@V (8x1).
#define QP 68
#define VP 72
#define PP 132
// floats: Qs 128*68, Ks 128*68, Vs 2x128*72, Ps 128*132
#define OFF_K  (128 * QP)
#define OFF_V  (2 * 128 * QP)
#define OFF_P  (2 * 128 * QP + 2 * 128 * VP)
#define ASMEM  ((2 * 128 * QP + 2 * 128 * VP + 128 * PP) * 4)

template <bool WM>
__global__ void __launch_bounds__(256) attn_mma(float* __restrict__ att)
{
    extern __shared__ float sm[];
    float* Qs = sm;
    float* Ks = sm + OFF_K;
    float* Vs = sm + OFF_V;
    float* Ps = sm + OFF_P;

    const int tid = threadIdx.x, wid = tid >> 5, lane = tid & 31;
    const int qr = lane >> 2, qk = lane & 3;
    const int b = blockIdx.z, h = blockIdx.y, r0 = blockIdx.x * 128;

    const float* qb = g_q + (size_t)(b * Ss + r0) * Hdim + h * DH;
    const float* kb = g_k + (size_t)(b * Ss) * Hdim + h * DH;
    const float* vb = g_v + (size_t)(b * Ss) * Hdim + h * DH;

    const uint32_t ksb = s2u(Ks), vsb = s2u(Vs);
    const int lr = tid >> 4, lc4 = (tid & 15) * 4;

    auto issueK = [&](int t) {
        const float* src = kb + (size_t)t * 128 * Hdim;
#pragma unroll
        for (int p = 0; p < 8; p++) {
            int r = lr + p * 16;
            cpa16(ksb + (uint32_t)(r * QP + lc4) * 4, src + (size_t)r * Hdim + lc4);
        }
        CPCOMMIT();
    };
    auto issueV = [&](int t) {
        const float* src = vb + (size_t)t * 128 * Hdim;
        const uint32_t base = vsb + (uint32_t)((t & 1) * 128 * VP) * 4;
#pragma unroll
        for (int p = 0; p < 8; p++) {
            int r = lr + p * 16;
            cpa16(base + (uint32_t)(r * VP + lc4) * 4, src + (size_t)r * Hdim + lc4);
        }
        CPCOMMIT();
    };

    // Q -> smem (tf32-rounded)
#pragma unroll
    for (int p = 0; p < 8; p++) {
        int r = lr + p * 16;
        float4 v = *(const float4*)(qb + (size_t)r * Hdim + lc4);
        v.x = tf32r(v.x); v.y = tf32r(v.y); v.z = tf32r(v.z); v.w = tf32r(v.w);
        *(float4*)&Qs[r * QP + lc4] = v;
    }
    issueK(0);
    issueV(0);

    float o[8][4];
#pragma unroll
    for (int ni = 0; ni < 8; ni++)
#pragma unroll
        for (int j = 0; j < 4; j++) o[ni][j] = 0.0f;

    const int wrS = 32 * (wid >> 1), wcS = 64 * (wid & 1);

    for (int kt = 0; kt < 16; kt++) {
        CPWAIT0();
        __syncthreads();

        // ---- S = Q @ K^T ----
        float s[2][8][4];
#pragma unroll
        for (int mi = 0; mi < 2; mi++)
#pragma unroll
            for (int ni = 0; ni < 8; ni++)
#pragma unroll
                for (int j = 0; j < 4; j++) s[mi][ni][j] = 0.0f;

#pragma unroll
        for (int ks = 0; ks < 8; ks++) {
            uint32_t af[2][4], bf[8][2];
#pragma unroll
            for (int mi = 0; mi < 2; mi++) {
                const float* ap = &Qs[(wrS + 16 * mi + qr) * QP + 8 * ks + qk];
                af[mi][0] = __float_as_uint(ap[0]);
                af[mi][1] = __float_as_uint(ap[8 * QP]);
                af[mi][2] = __float_as_uint(ap[4]);
                af[mi][3] = __float_as_uint(ap[8 * QP + 4]);
            }
#pragma unroll
            for (int ni = 0; ni < 8; ni++) {
                const float* bp = &Ks[(wcS + 8 * ni + qr) * QP + 8 * ks + qk];
                bf[ni][0] = tf32u(bp[0]);   // K arrived raw fp32 via cp.async
                bf[ni][1] = tf32u(bp[4]);
            }
#pragma unroll
            for (int mi = 0; mi < 2; mi++)
#pragma unroll
                for (int ni = 0; ni < 8; ni++)
                    mma8(s[mi][ni], af[mi], bf[ni]);
        }

        // ---- sigmoid -> att_map + Ps ----
#pragma unroll
        for (int mi = 0; mi < 2; mi++) {
            const int rr = wrS + 16 * mi + qr;
#pragma unroll
            for (int ni = 0; ni < 8; ni++) {
                const int cc = wcS + 8 * ni + 2 * qk;
                const float p0 = sigm(s[mi][ni][0]);
                const float p1 = sigm(s[mi][ni][1]);
                const float p2 = sigm(s[mi][ni][2]);
                const float p3 = sigm(s[mi][ni][3]);
                if (WM) {
                    size_t base = ((size_t)((b * NH + h) * Ss) + r0 + rr) * Ss
                                + (size_t)kt * 128 + cc;
                    *(float2*)(att + base) = make_float2(p0, p1);
                    *(float2*)(att + base + 8 * (size_t)Ss) = make_float2(p2, p3);
                }
                *(float2*)&Ps[rr * PP + cc] = make_float2(tf32r(p0), tf32r(p1));
                *(float2*)&Ps[(rr + 8) * PP + cc] = make_float2(tf32r(p2), tf32r(p3));
            }
        }
        __syncthreads();  // Ps ready; all warps done with Ks

        if (kt < 15) { issueK(kt + 1); issueV(kt + 1); }

        // ---- O += P @ V ----
        const float* Vt = Vs + (kt & 1) * 128 * VP;
#pragma unroll
        for (int ks = 0; ks < 16; ks++) {
            uint32_t af[4];
            const float* ap = &Ps[(16 * wid + qr) * PP + 8 * ks + qk];
            af[0] = __float_as_uint(ap[0]);
            af[1] = __float_as_uint(ap[8 * PP]);
            af[2] = __float_as_uint(ap[4]);
            af[3] = __float_as_uint(ap[8 * PP + 4]);
#pragma unroll
            for (int ni = 0; ni < 8; ni++) {
                uint32_t bf[2];
                const float* bp = &Vt[(8 * ks + qk) * VP + 8 * ni + qr];
                bf[0] = tf32u(bp[0]);       // V raw fp32 via cp.async
                bf[1] = tf32u(bp[4 * VP]);
                mma8(o[ni], af, bf);
            }
        }
        __syncthreads();  // Ps (and this V buffer) free for next iter
    }

    // ---- write O to g_o ----
    const int row = r0 + 16 * wid + qr;
    float* ob = g_o + (size_t)(b * Ss + row) * Hdim + h * DH;
#pragma unroll
    for (int ni = 0; ni < 8; ni++) {
        const int col = 8 * ni + 2 * qk;
        *(float2*)(ob + col) = make_float2(o[ni][0], o[ni][1]);
        *(float2*)(ob + 8 * (size_t)Hdim + col) = make_float2(o[ni][2], o[ni][3]);
    }
}

// ---------------------------------------------------------------------------
extern "C" void kernel_launch(void* const* d_in, const int* in_sizes, int n_in,
                              void* d_out, int out_size)
{
    (void)in_sizes; (void)n_in;
    const float* v  = (const float*)d_in[0];
    const float* k  = (const float*)d_in[1];
    const float* q  = (const float*)d_in[2];
    const float* Wv = (const float*)d_in[3];
    const float* bv = (const float*)d_in[4];
    const float* Wk = (const float*)d_in[5];
    const float* bk = (const float*)d_in[6];
    const float* Wq = (const float*)d_in[7];
    const float* bq = (const float*)d_in[8];
    const float* Wm = (const float*)d_in[9];
    const float* bm = (const float*)d_in[10];
    float* out = (float*)d_out;

    float *gq, *gk, *gv, *go;
    cudaGetSymbolAddress((void**)&gq, g_q);
    cudaGetSymbolAddress((void**)&gk, g_k);
    cudaGetSymbolAddress((void**)&gv, g_v);
    cudaGetSymbolAddress((void**)&go, g_o);

    cudaFuncSetAttribute(attn_mma<true>,  cudaFuncAttributeMaxDynamicSharedMemorySize, ASMEM);
    cudaFuncSetAttribute(attn_mma<false>, cudaFuncAttributeMaxDynamicSharedMemorySize, ASMEM);

    dim3 gg(Hdim / 128, MT / 128);  // (8, 32)
    gemm_mma<<<gg, 256>>>(q, Wq, bq, gq);
    gemm_mma<<<gg, 256>>>(k, Wk, bk, gk);
    gemm_mma<<<gg, 256>>>(v, Wv, bv, gv);

    const long long atted_elems = (long long)MT * Hdim;          // 4,194,304
    const long long map_elems   = (long long)Bb * NH * Ss * Ss;  // 134,217,728
    dim3 ga(Ss / 128, NH, Bb);  // (16, 16, 2)
    if ((long long)out_size >= atted_elems + map_elems) {
        attn_mma<true><<<ga, 256, ASMEM>>>(out + (size_t)atted_elems);
    } else {
        attn_mma<false><<<ga, 256, ASMEM>>>(nullptr);
    }

    gemm_mma<<<gg, 256>>>(go, Wm, bm, out);
}

// round 8
// speedup vs baseline: 2.9940x; 1.1227x over previous
#include <cuda_runtime.h>
#include <cstdint>
#include <math.h>

#define Hdim  1024
#define NH    16
#define DH    64
#define BATCH 2
#define Ss    2048
#define MT    (BATCH * Ss)

// Scratch (no allocs allowed)
__device__ float g_q[MT * Hdim];
__device__ float g_k[MT * Hdim];
__device__ float g_v[MT * Hdim];
__device__ float g_o[MT * Hdim];

// ======================= helpers =======================
__device__ __forceinline__ uint32_t s2u(const void* p) {
    uint32_t a;
    asm("{ .reg .u64 t; cvta.to.shared.u64 t, %1; cvt.u32.u64 %0, t; }"
        : "=r"(a) : "l"(p));
    return a;
}
__device__ __forceinline__ float tf32r(float x) {
    uint32_t u;
    asm("cvt.rna.tf32.f32 %0, %1;" : "=r"(u) : "f"(x));
    return __uint_as_float(u);
}
__device__ __forceinline__ uint32_t tf32u(float x) {
    uint32_t u;
    asm("cvt.rna.tf32.f32 %0, %1;" : "=r"(u) : "f"(x));
    return u;
}
__device__ __forceinline__ void mma8(float* c, const uint32_t* a, const uint32_t* b) {
    asm volatile(
        "mma.sync.aligned.m16n8k8.row.col.f32.tf32.tf32.f32 "
        "{%0,%1,%2,%3}, {%4,%5,%6,%7}, {%8,%9}, {%0,%1,%2,%3};\n"
        : "+f"(c[0]), "+f"(c[1]), "+f"(c[2]), "+f"(c[3])
        : "r"(a[0]), "r"(a[1]), "r"(a[2]), "r"(a[3]), "r"(b[0]), "r"(b[1]));
}
__device__ __forceinline__ void cpa16(uint32_t dst, const void* src) {
    asm volatile("cp.async.cg.shared.global [%0], [%1], 16;" :: "r"(dst), "l"(src));
}
#define CPCOMMIT() asm volatile("cp.async.commit_group;" ::: "memory")
#define CPWAIT0()  asm volatile("cp.async.wait_group 0;" ::: "memory")
#define CPWAIT1()  asm volatile("cp.async.wait_group 1;" ::: "memory")

__device__ __forceinline__ float sigm(float x) {
    return 1.0f / (1.0f + __expf(-0.125f * x));
}

// ======================= projection GEMM (cp.async 2-stage) =======================
// out[M,N] = A[M,K] @ W[N,K]^T + bias.  CTA 128x128, BK=32, 256 thr, 2 stages.
#define GP  36
#define GST (128 * GP)
#define GSMEM (4 * GST * 4)

__global__ void __launch_bounds__(256, 2) gemm_mma(
    const float* __restrict__ A, const float* __restrict__ W,
    const float* __restrict__ bias, float* __restrict__ out)
{
    extern __shared__ float gsm[];
    float* As = gsm;             // [2][GST]
    float* Bs = gsm + 2 * GST;   // [2][GST]

    const int tid = threadIdx.x, wid = tid >> 5, lane = tid & 31;
    const int qr = lane >> 2, qk = lane & 3;
    const int wr = (wid >> 1) * 32, wc = (wid & 1) * 64;
    const int m0 = blockIdx.y * 128, n0 = blockIdx.x * 128;
    const int lr = tid >> 3, lc4 = (tid & 7) * 4;

    auto issue = [&](int kc, int st) {
        const float* Ap = A + (size_t)m0 * Hdim + kc * 32;
        const float* Wp = W + (size_t)n0 * Hdim + kc * 32;
        const uint32_t ab = s2u(As + st * GST), bb = s2u(Bs + st * GST);
#pragma unroll
        for (int p = 0; p < 4; p++) {
            const int r = lr + p * 32;
            const uint32_t so = (uint32_t)(r * GP + lc4) * 4;
            cpa16(ab + so, Ap + (size_t)r * Hdim + lc4);
            cpa16(bb + so, Wp + (size_t)r * Hdim + lc4);
        }
        CPCOMMIT();
    };

    float c[2][8][4];
#pragma unroll
    for (int mi = 0; mi < 2; mi++)
#pragma unroll
        for (int ni = 0; ni < 8; ni++)
#pragma unroll
            for (int j = 0; j < 4; j++) c[mi][ni][j] = 0.0f;

    issue(0, 0);
    for (int kc = 0; kc < 32; kc++) {
        if (kc < 31) { issue(kc + 1, (kc + 1) & 1); CPWAIT1(); }
        else         { CPWAIT0(); }
        __syncthreads();
        const float* Abuf = As + (kc & 1) * GST;
        const float* Bbuf = Bs + (kc & 1) * GST;
#pragma unroll
        for (int ks = 0; ks < 4; ks++) {
            uint32_t af[2][4], bf[8][2];
#pragma unroll
            for (int mi = 0; mi < 2; mi++) {
                const float* ap = &Abuf[(wr + 16 * mi + qr) * GP + 8 * ks + qk];
                af[mi][0] = tf32u(ap[0]);
                af[mi][1] = tf32u(ap[8 * GP]);
                af[mi][2] = tf32u(ap[4]);
                af[mi][3] = tf32u(ap[8 * GP + 4]);
            }
#pragma unroll
            for (int ni = 0; ni < 8; ni++) {
                const float* bp = &Bbuf[(wc + 8 * ni + qr) * GP + 8 * ks + qk];
                bf[ni][0] = tf32u(bp[0]);
                bf[ni][1] = tf32u(bp[4]);
            }
#pragma unroll
            for (int mi = 0; mi < 2; mi++)
#pragma unroll
                for (int ni = 0; ni < 8; ni++)
                    mma8(c[mi][ni], af[mi], bf[ni]);
        }
        __syncthreads();
    }

#pragma unroll
    for (int mi = 0; mi < 2; mi++) {
        const int row = m0 + wr + 16 * mi + qr;
#pragma unroll
        for (int ni = 0; ni < 8; ni++) {
            const int col = n0 + wc + 8 * ni + 2 * qk;
            const float b0 = bias[col], b1 = bias[col + 1];
            *(float2*)(out + (size_t)row * Hdim + col) =
                make_float2(c[mi][ni][0] + b0, c[mi][ni][1] + b1);
            *(float2*)(out + (size_t)(row + 8) * Hdim + col) =
                make_float2(c[mi][ni][2] + b0, c[mi][ni][3] + b1);
        }
    }
}

// ======================= fused sigmoid attention =======================
// Grid (32, NH, BATCH), 256 thr, 64 q-rows/CTA, key tiles of 128.
// Swizzled smem (col ^= (row&7)<<2): Qs 16K, Ks 32K, Vs 32K, Ps 32K = 112K -> 2 CTA/SM.
#define AK  (64 * 64)
#define AV  (AK + 128 * 64)
#define AP  (AV + 128 * 64)
#define ASZ (AP + 64 * 128)
#define ASMEM (ASZ * 4)

template <bool WM>
__global__ void __launch_bounds__(256, 2) attn_mma(float* __restrict__ att)
{
    extern __shared__ float sm[];
    float* Qs = sm;
    float* Ks = sm + AK;
    float* Vs = sm + AV;
    float* Ps = sm + AP;

    const int tid = threadIdx.x, wid = tid >> 5, lane = tid & 31;
    const int qr = lane >> 2, qk = lane & 3;
    const int sw = qr << 2;
    const int b = blockIdx.z, h = blockIdx.y, r0 = blockIdx.x * 64;

    const float* qb = g_q + (size_t)(b * Ss + r0) * Hdim + h * DH;
    const float* kb = g_k + (size_t)(b * Ss) * Hdim + h * DH;
    const float* vb = g_v + (size_t)(b * Ss) * Hdim + h * DH;

    const uint32_t ksb = s2u(Ks), vsb = s2u(Vs);

    auto issueK = [&](int t) {
        const float* src = kb + (size_t)t * 128 * Hdim;
#pragma unroll
        for (int p = 0; p < 8; p++) {
            const int j = tid + p * 256;
            const int row = j >> 4, c4 = (j & 15) * 4;
            const int cs = c4 ^ ((row & 7) << 2);
            cpa16(ksb + (uint32_t)(row * 64 + cs) * 4, src + (size_t)row * Hdim + c4);
        }
        CPCOMMIT();
    };
    auto issueV = [&](int t) {
        const float* src = vb + (size_t)t * 128 * Hdim;
#pragma unroll
        for (int p = 0; p < 8; p++) {
            const int j = tid + p * 256;
            const int row = j >> 4, c4 = (j & 15) * 4;
            const int cs = c4 ^ ((row & 7) << 2);
            cpa16(vsb + (uint32_t)(row * 64 + cs) * 4, src + (size_t)row * Hdim + c4);
        }
        CPCOMMIT();
    };

    // Q -> smem (tf32-rounded, swizzled)
#pragma unroll
    for (int p = 0; p < 4; p++) {
        const int j = tid + p * 256;
        const int row = j >> 4, c4 = (j & 15) * 4;
        float4 v = *(const float4*)(qb + (size_t)row * Hdim + c4);
        v.x = tf32r(v.x); v.y = tf32r(v.y); v.z = tf32r(v.z); v.w = tf32r(v.w);
        *(float4*)&Qs[row * 64 + (c4 ^ ((row & 7) << 2))] = v;
    }
    issueK(0);
    issueV(0);

    float o[4][4];
#pragma unroll
    for (int ni = 0; ni < 4; ni++)
#pragma unroll
        for (int j = 0; j < 4; j++) o[ni][j] = 0.0f;

    const int wrS = 16 * (wid >> 1);       // q-row group (also PV row group)
    const int wcS = 64 * (wid & 1);        // S col group
    const int wcP = 32 * (wid & 1);        // PV col group

    for (int kt = 0; kt < 16; kt++) {
        CPWAIT0();
        __syncthreads();

        // ---- S = Q @ K^T ----
        float s[8][4];
#pragma unroll
        for (int ni = 0; ni < 8; ni++)
#pragma unroll
            for (int j = 0; j < 4; j++) s[ni][j] = 0.0f;

#pragma unroll
        for (int ks = 0; ks < 8; ks++) {
            const int c0 = (8 * ks + qk) ^ sw;
            const int c1 = (8 * ks + qk + 4) ^ sw;
            const int row0 = wrS + qr;
            uint32_t af[4];
            af[0] = __float_as_uint(Qs[row0 * 64 + c0]);
            af[1] = __float_as_uint(Qs[(row0 + 8) * 64 + c0]);
            af[2] = __float_as_uint(Qs[row0 * 64 + c1]);
            af[3] = __float_as_uint(Qs[(row0 + 8) * 64 + c1]);
#pragma unroll
            for (int ni = 0; ni < 8; ni++) {
                const int br = wcS + 8 * ni + qr;
                uint32_t bf[2];
                bf[0] = tf32u(Ks[br * 64 + c0]);
                bf[1] = tf32u(Ks[br * 64 + c1]);
                mma8(s[ni], af, bf);
            }
        }

        // ---- sigmoid -> att_map + Ps ----
        {
            const int rr = wrS + qr;
#pragma unroll
            for (int ni = 0; ni < 8; ni++) {
                const int cc = wcS + 8 * ni + 2 * qk;
                const float p0 = sigm(s[ni][0]);
                const float p1 = sigm(s[ni][1]);
                const float p2 = sigm(s[ni][2]);
                const float p3 = sigm(s[ni][3]);
                if (WM) {
                    size_t base = ((size_t)((b * NH + h) * Ss) + r0 + rr) * Ss
                                + (size_t)kt * 128 + cc;
                    *(float2*)(att + base) = make_float2(p0, p1);
                    *(float2*)(att + base + 8 * (size_t)Ss) = make_float2(p2, p3);
                }
                const int pc = cc ^ sw;
                *(float2*)&Ps[rr * 128 + pc] = make_float2(tf32r(p0), tf32r(p1));
                *(float2*)&Ps[(rr + 8) * 128 + pc] = make_float2(tf32r(p2), tf32r(p3));
            }
        }
        __syncthreads();  // Ps ready; Ks free

        if (kt < 15) issueK(kt + 1);  // overlaps PV below

        // ---- O += P @ V ----
#pragma unroll
        for (int ks = 0; ks < 16; ks++) {
            const int pc0 = (8 * ks + qk) ^ sw;
            const int pc1 = (8 * ks + qk + 4) ^ sw;
            const int prow = wrS + qr;
            uint32_t af[4];
            af[0] = __float_as_uint(Ps[prow * 128 + pc0]);
            af[1] = __float_as_uint(Ps[(prow + 8) * 128 + pc0]);
            af[2] = __float_as_uint(Ps[prow * 128 + pc1]);
            af[3] = __float_as_uint(Ps[(prow + 8) * 128 + pc1]);
            const int vr0 = 8 * ks + qk, vr1 = vr0 + 4;
            const int sv0 = qk << 2, sv1 = (qk + 4) << 2;
#pragma unroll
            for (int ni = 0; ni < 4; ni++) {
                const int vc = wcP + 8 * ni + qr;
                uint32_t bf[2];
                bf[0] = tf32u(Vs[vr0 * 64 + (vc ^ sv0)]);
                bf[1] = tf32u(Vs[vr1 * 64 + (vc ^ sv1)]);
                mma8(o[ni], af, bf);
            }
        }
        __syncthreads();  // Vs free

        if (kt < 15) issueV(kt + 1);
    }

    // ---- write O ----
    const int row = r0 + wrS + qr;
    float* ob = g_o + (size_t)(b * Ss + row) * Hdim + h * DH;
#pragma unroll
    for (int ni = 0; ni < 4; ni++) {
        const int col = wcP + 8 * ni + 2 * qk;
        *(float2*)(ob + col) = make_float2(o[ni][0], o[ni][1]);
        *(float2*)(ob + 8 * (size_t)Hdim + col) = make_float2(o[ni][2], o[ni][3]);
    }
}

// ---------------------------------------------------------------------------
extern "C" void kernel_launch(void* const* d_in, const int* in_sizes, int n_in,
                              void* d_out, int out_size)
{
    (void)in_sizes; (void)n_in;
    const float* v  = (const float*)d_in[0];
    const float* k  = (const float*)d_in[1];
    const float* q  = (const float*)d_in[2];
    const float* Wv = (const float*)d_in[3];
    const float* bv = (const float*)d_in[4];
    const float* Wk = (const float*)d_in[5];
    const float* bk = (const float*)d_in[6];
    const float* Wq = (const float*)d_in[7];
    const float* bq = (const float*)d_in[8];
    const float* Wm = (const float*)d_in[9];
    const float* bm = (const float*)d_in[10];
    float* out = (float*)d_out;

    float *gq, *gk, *gv, *go;
    cudaGetSymbolAddress((void**)&gq, g_q);
    cudaGetSymbolAddress((void**)&gk, g_k);
    cudaGetSymbolAddress((void**)&gv, g_v);
    cudaGetSymbolAddress((void**)&go, g_o);

    cudaFuncSetAttribute(gemm_mma, cudaFuncAttributeMaxDynamicSharedMemorySize, GSMEM);
    cudaFuncSetAttribute(attn_mma<true>,  cudaFuncAttributeMaxDynamicSharedMemorySize, ASMEM);
    cudaFuncSetAttribute(attn_mma<false>, cudaFuncAttributeMaxDynamicSharedMemorySize, ASMEM);

    dim3 gg(Hdim / 128, MT / 128);  // (8, 32)
    gemm_mma<<<gg, 256, GSMEM>>>(q, Wq, bq, gq);
    gemm_mma<<<gg, 256, GSMEM>>>(k, Wk, bk, gk);
    gemm_mma<<<gg, 256, GSMEM>>>(v, Wv, bv, gv);

    const long long atted_elems = (long long)MT * Hdim;             // 4,194,304
    const long long map_elems   = (long long)BATCH * NH * Ss * Ss;  // 134,217,728
    dim3 ga(Ss / 64, NH, BATCH);  // (32, 16, 2)
    if ((long long)out_size >= atted_elems + map_elems) {
        attn_mma<true><<<ga, 256, ASMEM>>>(out + (size_t)atted_elems);
    } else {
        attn_mma<false><<<ga, 256, ASMEM>>>(nullptr);
    }

    gemm_mma<<<gg, 256, GSMEM>>>(go, Wm, bm, out);
}

// round 9
// speedup vs baseline: 3.0705x; 1.0255x over previous
#include <cuda_runtime.h>
#include <cstdint>
#include <math.h>

#define Hdim  1024
#define NH    16
#define DH    64
#define BATCH 2
#define Ss    2048
#define MT    (BATCH * Ss)

// Scratch (no allocs allowed)
__device__ float g_q[MT * Hdim];
__device__ float g_k[MT * Hdim];
__device__ float g_v[MT * Hdim];
__device__ float g_o[MT * Hdim];

// ======================= helpers =======================
__device__ __forceinline__ uint32_t s2u(const void* p) {
    uint32_t a;
    asm("{ .reg .u64 t; cvta.to.shared.u64 t, %1; cvt.u32.u64 %0, t; }"
        : "=r"(a) : "l"(p));
    return a;
}
__device__ __forceinline__ float tf32r(float x) {
    uint32_t u;
    asm("cvt.rna.tf32.f32 %0, %1;" : "=r"(u) : "f"(x));
    return __uint_as_float(u);
}
__device__ __forceinline__ uint32_t tf32u(float x) {
    uint32_t u;
    asm("cvt.rna.tf32.f32 %0, %1;" : "=r"(u) : "f"(x));
    return u;
}
__device__ __forceinline__ void mma8(float* c, const uint32_t* a, const uint32_t* b) {
    asm volatile(
        "mma.sync.aligned.m16n8k8.row.col.f32.tf32.tf32.f32 "
        "{%0,%1,%2,%3}, {%4,%5,%6,%7}, {%8,%9}, {%0,%1,%2,%3};\n"
        : "+f"(c[0]), "+f"(c[1]), "+f"(c[2]), "+f"(c[3])
        : "r"(a[0]), "r"(a[1]), "r"(a[2]), "r"(a[3]), "r"(b[0]), "r"(b[1]));
}
__device__ __forceinline__ void cpa16(uint32_t dst, const void* src) {
    asm volatile("cp.async.cg.shared.global [%0], [%1], 16;" :: "r"(dst), "l"(src));
}
#define CPCOMMIT() asm volatile("cp.async.commit_group;" ::: "memory")
#define CPWAIT0()  asm volatile("cp.async.wait_group 0;" ::: "memory")
#define CPWAIT1()  asm volatile("cp.async.wait_group 1;" ::: "memory")

__device__ __forceinline__ float sigm(float x) {
    return 1.0f / (1.0f + __expf(-0.125f * x));
}

// ======================= projection GEMM (cp.async 2-stage) =======================
// out[M,N] = A[M,K] @ W[N,K]^T + bias.  CTA 128x128, BK=32, 256 thr, 2 stages.
// RND: round the epilogue output to tf32 (for q/k/v scratch consumed by MMA).
#define GP  36
#define GST (128 * GP)
#define GSMEM (4 * GST * 4)

template <bool RND>
__global__ void __launch_bounds__(256, 2) gemm_mma(
    const float* __restrict__ A, const float* __restrict__ W,
    const float* __restrict__ bias, float* __restrict__ out)
{
    extern __shared__ float gsm[];
    float* As = gsm;             // [2][GST]
    float* Bs = gsm + 2 * GST;   // [2][GST]

    const int tid = threadIdx.x, wid = tid >> 5, lane = tid & 31;
    const int qr = lane >> 2, qk = lane & 3;
    const int wr = (wid >> 1) * 32, wc = (wid & 1) * 64;
    const int m0 = blockIdx.y * 128, n0 = blockIdx.x * 128;
    const int lr = tid >> 3, lc4 = (tid & 7) * 4;

    auto issue = [&](int kc, int st) {
        const float* Ap = A + (size_t)m0 * Hdim + kc * 32;
        const float* Wp = W + (size_t)n0 * Hdim + kc * 32;
        const uint32_t ab = s2u(As + st * GST), bb = s2u(Bs + st * GST);
#pragma unroll
        for (int p = 0; p < 4; p++) {
            const int r = lr + p * 32;
            const uint32_t so = (uint32_t)(r * GP + lc4) * 4;
            cpa16(ab + so, Ap + (size_t)r * Hdim + lc4);
            cpa16(bb + so, Wp + (size_t)r * Hdim + lc4);
        }
        CPCOMMIT();
    };

    float c[2][8][4];
#pragma unroll
    for (int mi = 0; mi < 2; mi++)
#pragma unroll
        for (int ni = 0; ni < 8; ni++)
#pragma unroll
            for (int j = 0; j < 4; j++) c[mi][ni][j] = 0.0f;

    issue(0, 0);
    for (int kc = 0; kc < 32; kc++) {
        if (kc < 31) { issue(kc + 1, (kc + 1) & 1); CPWAIT1(); }
        else         { CPWAIT0(); }
        __syncthreads();
        const float* Abuf = As + (kc & 1) * GST;
        const float* Bbuf = Bs + (kc & 1) * GST;
#pragma unroll
        for (int ks = 0; ks < 4; ks++) {
            uint32_t af[2][4], bf[8][2];
#pragma unroll
            for (int mi = 0; mi < 2; mi++) {
                const float* ap = &Abuf[(wr + 16 * mi + qr) * GP + 8 * ks + qk];
                af[mi][0] = tf32u(ap[0]);
                af[mi][1] = tf32u(ap[8 * GP]);
                af[mi][2] = tf32u(ap[4]);
                af[mi][3] = tf32u(ap[8 * GP + 4]);
            }
#pragma unroll
            for (int ni = 0; ni < 8; ni++) {
                const float* bp = &Bbuf[(wc + 8 * ni + qr) * GP + 8 * ks + qk];
                bf[ni][0] = tf32u(bp[0]);
                bf[ni][1] = tf32u(bp[4]);
            }
#pragma unroll
            for (int mi = 0; mi < 2; mi++)
#pragma unroll
                for (int ni = 0; ni < 8; ni++)
                    mma8(c[mi][ni], af[mi], bf[ni]);
        }
        __syncthreads();
    }

#pragma unroll
    for (int mi = 0; mi < 2; mi++) {
        const int row = m0 + wr + 16 * mi + qr;
#pragma unroll
        for (int ni = 0; ni < 8; ni++) {
            const int col = n0 + wc + 8 * ni + 2 * qk;
            const float b0 = bias[col], b1 = bias[col + 1];
            float o00 = c[mi][ni][0] + b0, o01 = c[mi][ni][1] + b1;
            float o10 = c[mi][ni][2] + b0, o11 = c[mi][ni][3] + b1;
            if (RND) { o00 = tf32r(o00); o01 = tf32r(o01);
                       o10 = tf32r(o10); o11 = tf32r(o11); }
            *(float2*)(out + (size_t)row * Hdim + col) = make_float2(o00, o01);
            *(float2*)(out + (size_t)(row + 8) * Hdim + col) = make_float2(o10, o11);
        }
    }
}

// ======================= fused sigmoid attention =======================
// Grid (32, NH, BATCH), 256 thr, 64 q-rows/CTA, key tiles of 128.
// Q/K/V in g_* are already tf32-rounded -> no cvt in the inner loops.
// Swizzled smem: Qs 16K, Ks 32K, Vs 32K, Ps 32K = 112K -> 2 CTA/SM.
// Split cp.async waits: top of iter waits only K; V waited after S+sigmoid.
#define AK  (64 * 64)
#define AV  (AK + 128 * 64)
#define AP  (AV + 128 * 64)
#define ASZ (AP + 64 * 128)
#define ASMEM (ASZ * 4)

template <bool WM>
__global__ void __launch_bounds__(256, 2) attn_mma(float* __restrict__ att)
{
    extern __shared__ float sm[];
    float* Qs = sm;
    float* Ks = sm + AK;
    float* Vs = sm + AV;
    float* Ps = sm + AP;

    const int tid = threadIdx.x, wid = tid >> 5, lane = tid & 31;
    const int qr = lane >> 2, qk = lane & 3;
    const int sw = qr << 2;
    const int b = blockIdx.z, h = blockIdx.y, r0 = blockIdx.x * 64;

    const float* qb = g_q + (size_t)(b * Ss + r0) * Hdim + h * DH;
    const float* kb = g_k + (size_t)(b * Ss) * Hdim + h * DH;
    const float* vb = g_v + (size_t)(b * Ss) * Hdim + h * DH;

    const uint32_t ksb = s2u(Ks), vsb = s2u(Vs);

    auto issueK = [&](int t) {
        const float* src = kb + (size_t)t * 128 * Hdim;
#pragma unroll
        for (int p = 0; p < 8; p++) {
            const int j = tid + p * 256;
            const int row = j >> 4, c4 = (j & 15) * 4;
            const int cs = c4 ^ ((row & 7) << 2);
            cpa16(ksb + (uint32_t)(row * 64 + cs) * 4, src + (size_t)row * Hdim + c4);
        }
        CPCOMMIT();
    };
    auto issueV = [&](int t) {
        const float* src = vb + (size_t)t * 128 * Hdim;
#pragma unroll
        for (int p = 0; p < 8; p++) {
            const int j = tid + p * 256;
            const int row = j >> 4, c4 = (j & 15) * 4;
            const int cs = c4 ^ ((row & 7) << 2);
            cpa16(vsb + (uint32_t)(row * 64 + cs) * 4, src + (size_t)row * Hdim + c4);
        }
        CPCOMMIT();
    };

    // Q -> smem (already tf32-rounded in g_q, swizzled)
#pragma unroll
    for (int p = 0; p < 4; p++) {
        const int j = tid + p * 256;
        const int row = j >> 4, c4 = (j & 15) * 4;
        float4 v = *(const float4*)(qb + (size_t)row * Hdim + c4);
        *(float4*)&Qs[row * 64 + (c4 ^ ((row & 7) << 2))] = v;
    }
    issueK(0);
    issueV(0);

    float o[4][4];
#pragma unroll
    for (int ni = 0; ni < 4; ni++)
#pragma unroll
        for (int j = 0; j < 4; j++) o[ni][j] = 0.0f;

    const int wrS = 16 * (wid >> 1);       // q-row group (also PV row group)
    const int wcS = 64 * (wid & 1);        // S col group
    const int wcP = 32 * (wid & 1);        // PV col group

    for (int kt = 0; kt < 16; kt++) {
        CPWAIT1();        // K(kt) landed; V(kt) may still be in flight
        __syncthreads();

        // ---- S = Q @ K^T ----
        float s[8][4];
#pragma unroll
        for (int ni = 0; ni < 8; ni++)
#pragma unroll
            for (int j = 0; j < 4; j++) s[ni][j] = 0.0f;

#pragma unroll
        for (int ks = 0; ks < 8; ks++) {
            const int c0 = (8 * ks + qk) ^ sw;
            const int c1 = (8 * ks + qk + 4) ^ sw;
            const int row0 = wrS + qr;
            uint32_t af[4];
            af[0] = __float_as_uint(Qs[row0 * 64 + c0]);
            af[1] = __float_as_uint(Qs[(row0 + 8) * 64 + c0]);
            af[2] = __float_as_uint(Qs[row0 * 64 + c1]);
            af[3] = __float_as_uint(Qs[(row0 + 8) * 64 + c1]);
#pragma unroll
            for (int ni = 0; ni < 8; ni++) {
                const int br = wcS + 8 * ni + qr;
                uint32_t bf[2];
                bf[0] = __float_as_uint(Ks[br * 64 + c0]);
                bf[1] = __float_as_uint(Ks[br * 64 + c1]);
                mma8(s[ni], af, bf);
            }
        }

        // ---- sigmoid -> att_map + Ps ----
        {
            const int rr = wrS + qr;
#pragma unroll
            for (int ni = 0; ni < 8; ni++) {
                const int cc = wcS + 8 * ni + 2 * qk;
                const float p0 = sigm(s[ni][0]);
                const float p1 = sigm(s[ni][1]);
                const float p2 = sigm(s[ni][2]);
                const float p3 = sigm(s[ni][3]);
                if (WM) {
                    size_t base = ((size_t)((b * NH + h) * Ss) + r0 + rr) * Ss
                                + (size_t)kt * 128 + cc;
                    *(float2*)(att + base) = make_float2(p0, p1);
                    *(float2*)(att + base + 8 * (size_t)Ss) = make_float2(p2, p3);
                }
                const int pc = cc ^ sw;
                *(float2*)&Ps[rr * 128 + pc] = make_float2(tf32r(p0), tf32r(p1));
                *(float2*)&Ps[(rr + 8) * 128 + pc] = make_float2(tf32r(p2), tf32r(p3));
            }
        }
        __syncthreads();  // Ps ready; Ks free

        if (kt < 15) { issueK(kt + 1); CPWAIT1(); }  // V(kt) landed
        else         { CPWAIT0(); }
        __syncthreads();  // Vs visible to all

        // ---- O += P @ V ----
#pragma unroll
        for (int ks = 0; ks < 16; ks++) {
            const int pc0 = (8 * ks + qk) ^ sw;
            const int pc1 = (8 * ks + qk + 4) ^ sw;
            const int prow = wrS + qr;
            uint32_t af[4];
            af[0] = __float_as_uint(Ps[prow * 128 + pc0]);
            af[1] = __float_as_uint(Ps[(prow + 8) * 128 + pc0]);
            af[2] = __float_as_uint(Ps[prow * 128 + pc1]);
            af[3] = __float_as_uint(Ps[(prow + 8) * 128 + pc1]);
            const int vr0 = 8 * ks + qk, vr1 = vr0 + 4;
            const int sv0 = qk << 2, sv1 = (qk + 4) << 2;
#pragma unroll
            for (int ni = 0; ni < 4; ni++) {
                const int vc = wcP + 8 * ni + qr;
                uint32_t bf[2];
                bf[0] = __float_as_uint(Vs[vr0 * 64 + (vc ^ sv0)]);
                bf[1] = __float_as_uint(Vs[vr1 * 64 + (vc ^ sv1)]);
                mma8(o[ni], af, bf);
            }
        }
        __syncthreads();  // Vs free

        if (kt < 15) issueV(kt + 1);
    }

    // ---- write O ----
    const int row = r0 + wrS + qr;
    float* ob = g_o + (size_t)(b * Ss + row) * Hdim + h * DH;
#pragma unroll
    for (int ni = 0; ni < 4; ni++) {
        const int col = wcP + 8 * ni + 2 * qk;
        *(float2*)(ob + col) = make_float2(o[ni][0], o[ni][1]);
        *(float2*)(ob + 8 * (size_t)Hdim + col) = make_float2(o[ni][2], o[ni][3]);
    }
}

// ---------------------------------------------------------------------------
extern "C" void kernel_launch(void* const* d_in, const int* in_sizes, int n_in,
                              void* d_out, int out_size)
{
    (void)in_sizes; (void)n_in;
    const float* v  = (const float*)d_in[0];
    const float* k  = (const float*)d_in[1];
    const float* q  = (const float*)d_in[2];
    const float* Wv = (const float*)d_in[3];
    const float* bv = (const float*)d_in[4];
    const float* Wk = (const float*)d_in[5];
    const float* bk = (const float*)d_in[6];
    const float* Wq = (const float*)d_in[7];
    const float* bq = (const float*)d_in[8];
    const float* Wm = (const float*)d_in[9];
    const float* bm = (const float*)d_in[10];
    float* out = (float*)d_out;

    float *gq, *gk, *gv, *go;
    cudaGetSymbolAddress((void**)&gq, g_q);
    cudaGetSymbolAddress((void**)&gk, g_k);
    cudaGetSymbolAddress((void**)&gv, g_v);
    cudaGetSymbolAddress((void**)&go, g_o);

    cudaFuncSetAttribute(gemm_mma<true>,  cudaFuncAttributeMaxDynamicSharedMemorySize, GSMEM);
    cudaFuncSetAttribute(gemm_mma<false>, cudaFuncAttributeMaxDynamicSharedMemorySize, GSMEM);
    cudaFuncSetAttribute(attn_mma<true>,  cudaFuncAttributeMaxDynamicSharedMemorySize, ASMEM);
    cudaFuncSetAttribute(attn_mma<false>, cudaFuncAttributeMaxDynamicSharedMemorySize, ASMEM);

    dim3 gg(Hdim / 128, MT / 128);  // (8, 32)
    gemm_mma<true><<<gg, 256, GSMEM>>>(q, Wq, bq, gq);
    gemm_mma<true><<<gg, 256, GSMEM>>>(k, Wk, bk, gk);
    gemm_mma<true><<<gg, 256, GSMEM>>>(v, Wv, bv, gv);

    const long long atted_elems = (long long)MT * Hdim;             // 4,194,304
    const long long map_elems   = (long long)BATCH * NH * Ss * Ss;  // 134,217,728
    dim3 ga(Ss / 64, NH, BATCH);  // (32, 16, 2)
    if ((long long)out_size >= atted_elems + map_elems) {
        attn_mma<true><<<ga, 256, ASMEM>>>(out + (size_t)atted_elems);
    } else {
        attn_mma<false><<<ga, 256, ASMEM>>>(nullptr);
    }

    gemm_mma<false><<<gg, 256, GSMEM>>>(go, Wm, bm, out);
}

// round 10
// speedup vs baseline: 3.1626x; 1.0300x over previous
#include <cuda_runtime.h>
#include <cstdint>
#include <math.h>

#define Hdim  1024
#define NH    16
#define DH    64
#define BATCH 2
#define Ss    2048
#define MT    (BATCH * Ss)

// Scratch (no allocs allowed)
__device__ float g_q[MT * Hdim];
__device__ float g_k[MT * Hdim];
__device__ float g_v[MT * Hdim];
__device__ float g_o[MT * Hdim];

// ======================= helpers =======================
__device__ __forceinline__ uint32_t s2u(const void* p) {
    uint32_t a;
    asm("{ .reg .u64 t; cvta.to.shared.u64 t, %1; cvt.u32.u64 %0, t; }"
        : "=r"(a) : "l"(p));
    return a;
}
__device__ __forceinline__ float tf32r(float x) {
    uint32_t u;
    asm("cvt.rna.tf32.f32 %0, %1;" : "=r"(u) : "f"(x));
    return __uint_as_float(u);
}
__device__ __forceinline__ uint32_t tf32u(float x) {
    uint32_t u;
    asm("cvt.rna.tf32.f32 %0, %1;" : "=r"(u) : "f"(x));
    return u;
}
__device__ __forceinline__ void mma8(float* c, const uint32_t* a, const uint32_t* b) {
    asm volatile(
        "mma.sync.aligned.m16n8k8.row.col.f32.tf32.tf32.f32 "
        "{%0,%1,%2,%3}, {%4,%5,%6,%7}, {%8,%9}, {%0,%1,%2,%3};\n"
        : "+f"(c[0]), "+f"(c[1]), "+f"(c[2]), "+f"(c[3])
        : "r"(a[0]), "r"(a[1]), "r"(a[2]), "r"(a[3]), "r"(b[0]), "r"(b[1]));
}
__device__ __forceinline__ void cpa16(uint32_t dst, const void* src) {
    asm volatile("cp.async.cg.shared.global [%0], [%1], 16;" :: "r"(dst), "l"(src));
}
#define CPCOMMIT() asm volatile("cp.async.commit_group;" ::: "memory")
#define CPWAIT0()  asm volatile("cp.async.wait_group 0;" ::: "memory")
#define CPWAIT1()  asm volatile("cp.async.wait_group 1;" ::: "memory")

__device__ __forceinline__ float sigm(float x) {
    return __fdividef(1.0f, 1.0f + __expf(-0.125f * x));
}

// ======================= projection GEMM (cp.async 2-stage) =======================
#define GP  36
#define GST (128 * GP)
#define GSMEM (4 * GST * 4)

template <bool RND>
__global__ void __launch_bounds__(256, 2) gemm_mma(
    const float* __restrict__ A, const float* __restrict__ W,
    const float* __restrict__ bias, float* __restrict__ out)
{
    extern __shared__ float gsm[];
    float* As = gsm;             // [2][GST]
    float* Bs = gsm + 2 * GST;   // [2][GST]

    const int tid = threadIdx.x, wid = tid >> 5, lane = tid & 31;
    const int qr = lane >> 2, qk = lane & 3;
    const int wr = (wid >> 1) * 32, wc = (wid & 1) * 64;
    const int m0 = blockIdx.y * 128, n0 = blockIdx.x * 128;
    const int lr = tid >> 3, lc4 = (tid & 7) * 4;

    auto issue = [&](int kc, int st) {
        const float* Ap = A + (size_t)m0 * Hdim + kc * 32;
        const float* Wp = W + (size_t)n0 * Hdim + kc * 32;
        const uint32_t ab = s2u(As + st * GST), bb = s2u(Bs + st * GST);
#pragma unroll
        for (int p = 0; p < 4; p++) {
            const int r = lr + p * 32;
            const uint32_t so = (uint32_t)(r * GP + lc4) * 4;
            cpa16(ab + so, Ap + (size_t)r * Hdim + lc4);
            cpa16(bb + so, Wp + (size_t)r * Hdim + lc4);
        }
        CPCOMMIT();
    };

    float c[2][8][4];
#pragma unroll
    for (int mi = 0; mi < 2; mi++)
#pragma unroll
        for (int ni = 0; ni < 8; ni++)
#pragma unroll
            for (int j = 0; j < 4; j++) c[mi][ni][j] = 0.0f;

    issue(0, 0);
    for (int kc = 0; kc < 32; kc++) {
        if (kc < 31) { issue(kc + 1, (kc + 1) & 1); CPWAIT1(); }
        else         { CPWAIT0(); }
        __syncthreads();
        const float* Abuf = As + (kc & 1) * GST;
        const float* Bbuf = Bs + (kc & 1) * GST;
#pragma unroll
        for (int ks = 0; ks < 4; ks++) {
            uint32_t af[2][4], bf[8][2];
#pragma unroll
            for (int mi = 0; mi < 2; mi++) {
                const float* ap = &Abuf[(wr + 16 * mi + qr) * GP + 8 * ks + qk];
                af[mi][0] = tf32u(ap[0]);
                af[mi][1] = tf32u(ap[8 * GP]);
                af[mi][2] = tf32u(ap[4]);
                af[mi][3] = tf32u(ap[8 * GP + 4]);
            }
#pragma unroll
            for (int ni = 0; ni < 8; ni++) {
                const float* bp = &Bbuf[(wc + 8 * ni + qr) * GP + 8 * ks + qk];
                bf[ni][0] = tf32u(bp[0]);
                bf[ni][1] = tf32u(bp[4]);
            }
#pragma unroll
            for (int mi = 0; mi < 2; mi++)
#pragma unroll
                for (int ni = 0; ni < 8; ni++)
                    mma8(c[mi][ni], af[mi], bf[ni]);
        }
        __syncthreads();
    }

#pragma unroll
    for (int mi = 0; mi < 2; mi++) {
        const int row = m0 + wr + 16 * mi + qr;
#pragma unroll
        for (int ni = 0; ni < 8; ni++) {
            const int col = n0 + wc + 8 * ni + 2 * qk;
            const float b0 = bias[col], b1 = bias[col + 1];
            float o00 = c[mi][ni][0] + b0, o01 = c[mi][ni][1] + b1;
            float o10 = c[mi][ni][2] + b0, o11 = c[mi][ni][3] + b1;
            if (RND) { o00 = tf32r(o00); o01 = tf32r(o01);
                       o10 = tf32r(o10); o11 = tf32r(o11); }
            *(float2*)(out + (size_t)row * Hdim + col) = make_float2(o00, o01);
            *(float2*)(out + (size_t)(row + 8) * Hdim + col) = make_float2(o10, o11);
        }
    }
}

// ======================= fused sigmoid attention (no-P-smem) =======================
// Grid (32, NH, BATCH), 128 thr (4 warps), 64 q-rows/CTA, key tiles of 128.
// Warp = 16 q-rows x all 128 key cols. Q in registers. P stays in registers:
// S C-frag == PV A-frag under key permutation l -> (l&1 ? 4+l/2 : l/2), applied
// to V's smem row placement. Smem = K 32K + V 32K = 64KB -> 3 CTAs/SM.
#define AV2   (128 * 64)
#define ASMEM (2 * 128 * 64 * 4)

template <bool WM>
__global__ void __launch_bounds__(128, 3) attn_mma(float* __restrict__ att)
{
    extern __shared__ float smr[];
    float* Ks = smr;
    float* Vs = smr + AV2;

    const int tid = threadIdx.x, wid = tid >> 5, lane = tid & 31;
    const int qr = lane >> 2, qk = lane & 3;
    const int b = blockIdx.z, h = blockIdx.y, r0 = blockIdx.x * 64;
    const int wrS = 16 * wid;

    const float* qb = g_q + (size_t)(b * Ss + r0) * Hdim + h * DH;
    const float* kb = g_k + (size_t)(b * Ss) * Hdim + h * DH;
    const float* vb = g_v + (size_t)(b * Ss) * Hdim + h * DH;

    const uint32_t ksb = s2u(Ks), vsb = s2u(Vs);

    auto issueK = [&](int t) {
        const float* src = kb + (size_t)t * 128 * Hdim;
#pragma unroll
        for (int p = 0; p < 16; p++) {
            const int j = tid + p * 128;
            const int row = j >> 4, c4 = (j & 15) * 4;
            const int cs = c4 ^ ((row & 7) << 2);
            cpa16(ksb + (uint32_t)(row * 64 + cs) * 4, src + (size_t)row * Hdim + c4);
        }
        CPCOMMIT();
    };
    auto issueV = [&](int t) {
        const float* src = vb + (size_t)t * 128 * Hdim;
#pragma unroll
        for (int p = 0; p < 16; p++) {
            const int j = tid + p * 128;
            const int row = j >> 4, c4 = (j & 15) * 4;
            const int l = row & 7;
            const int prow = (row & ~7) | ((l & 1) ? 4 + (l >> 1) : (l >> 1));
            const int cs = c4 ^ ((prow & 7) << 2);
            cpa16(vsb + (uint32_t)(prow * 64 + cs) * 4, src + (size_t)row * Hdim + c4);
        }
        CPCOMMIT();
    };

    issueK(0);
    issueV(0);

    // Q fragments in registers (g_q already tf32-rounded)
    uint32_t qf[8][4];
    {
        const float* q0 = qb + (size_t)(wrS + qr) * Hdim;
        const float* q1 = q0 + 8 * (size_t)Hdim;
#pragma unroll
        for (int ks = 0; ks < 8; ks++) {
            qf[ks][0] = __float_as_uint(q0[8 * ks + qk]);
            qf[ks][1] = __float_as_uint(q1[8 * ks + qk]);
            qf[ks][2] = __float_as_uint(q0[8 * ks + qk + 4]);
            qf[ks][3] = __float_as_uint(q1[8 * ks + qk + 4]);
        }
    }

    float o[8][4];
#pragma unroll
    for (int ni = 0; ni < 8; ni++)
#pragma unroll
        for (int j = 0; j < 4; j++) o[ni][j] = 0.0f;

    for (int kt = 0; kt < 16; kt++) {
        CPWAIT1();        // K(kt) landed; V(kt) may still be in flight
        __syncthreads();

        // ---- S = Q @ K^T : warp tile 16 x 128 ----
        float s[16][4];
#pragma unroll
        for (int ni = 0; ni < 16; ni++)
#pragma unroll
            for (int j = 0; j < 4; j++) s[ni][j] = 0.0f;

#pragma unroll
        for (int ks = 0; ks < 8; ks++) {
            const int c0 = (8 * ks + qk) ^ (qr << 2);
            const int c1 = c0 ^ 4;
#pragma unroll
            for (int ni = 0; ni < 16; ni++) {
                const int br = 8 * ni + qr;
                uint32_t bf[2];
                bf[0] = __float_as_uint(Ks[br * 64 + c0]);
                bf[1] = __float_as_uint(Ks[br * 64 + c1]);
                mma8(s[ni], qf[ks], bf);
            }
        }
        __syncthreads();  // Ks consumed

        if (kt < 15) issueK(kt + 1);

        // ---- sigmoid -> att_map; convert P in registers ----
        {
            const int rr = wrS + qr;
#pragma unroll
            for (int ni = 0; ni < 16; ni++) {
                const float p0 = sigm(s[ni][0]);
                const float p1 = sigm(s[ni][1]);
                const float p2 = sigm(s[ni][2]);
                const float p3 = sigm(s[ni][3]);
                if (WM) {
                    const int cc = 8 * ni + 2 * qk;
                    size_t base = ((size_t)((b * NH + h) * Ss) + r0 + rr) * Ss
                                + (size_t)kt * 128 + cc;
                    *(float2*)(att + base) = make_float2(p0, p1);
                    *(float2*)(att + base + 8 * (size_t)Ss) = make_float2(p2, p3);
                }
                s[ni][0] = tf32r(p0);
                s[ni][1] = tf32r(p1);
                s[ni][2] = tf32r(p2);
                s[ni][3] = tf32r(p3);
            }
        }

        if (kt < 15) { CPWAIT1(); }  // V(kt) landed (K(kt+1) in flight)
        else         { CPWAIT0(); }
        __syncthreads();  // Vs visible

        // ---- O += P @ V : A-frag = {c0, c2, c1, c3} of S, V rows permuted ----
#pragma unroll
        for (int ks = 0; ks < 16; ks++) {
            uint32_t af[4];
            af[0] = __float_as_uint(s[ks][0]);
            af[1] = __float_as_uint(s[ks][2]);
            af[2] = __float_as_uint(s[ks][1]);
            af[3] = __float_as_uint(s[ks][3]);
            const int vr0 = 8 * ks + qk, vr1 = vr0 + 4;
            const int sv0 = qk << 2, sv1 = (qk + 4) << 2;
#pragma unroll
            for (int ni = 0; ni < 8; ni++) {
                const int vc = 8 * ni + qr;
                uint32_t bf[2];
                bf[0] = __float_as_uint(Vs[vr0 * 64 + (vc ^ sv0)]);
                bf[1] = __float_as_uint(Vs[vr1 * 64 + (vc ^ sv1)]);
                mma8(o[ni], af, bf);
            }
        }
        __syncthreads();  // Vs consumed

        if (kt < 15) issueV(kt + 1);
    }

    // ---- write O ----
    const int row = r0 + wrS + qr;
    float* ob = g_o + (size_t)(b * Ss + row) * Hdim + h * DH;
#pragma unroll
    for (int ni = 0; ni < 8; ni++) {
        const int col = 8 * ni + 2 * qk;
        *(float2*)(ob + col) = make_float2(o[ni][0], o[ni][1]);
        *(float2*)(ob + 8 * (size_t)Hdim + col) = make_float2(o[ni][2], o[ni][3]);
    }
}

// ---------------------------------------------------------------------------
extern "C" void kernel_launch(void* const* d_in, const int* in_sizes, int n_in,
                              void* d_out, int out_size)
{
    (void)in_sizes; (void)n_in;
    const float* v  = (const float*)d_in[0];
    const float* k  = (const float*)d_in[1];
    const float* q  = (const float*)d_in[2];
    const float* Wv = (const float*)d_in[3];
    const float* bv = (const float*)d_in[4];
    const float* Wk = (const float*)d_in[5];
    const float* bk = (const float*)d_in[6];
    const float* Wq = (const float*)d_in[7];
    const float* bq = (const float*)d_in[8];
    const float* Wm = (const float*)d_in[9];
    const float* bm = (const float*)d_in[10];
    float* out = (float*)d_out;

    float *gq, *gk, *gv, *go;
    cudaGetSymbolAddress((void**)&gq, g_q);
    cudaGetSymbolAddress((void**)&gk, g_k);
    cudaGetSymbolAddress((void**)&gv, g_v);
    cudaGetSymbolAddress((void**)&go, g_o);

    cudaFuncSetAttribute(gemm_mma<true>,  cudaFuncAttributeMaxDynamicSharedMemorySize, GSMEM);
    cudaFuncSetAttribute(gemm_mma<false>, cudaFuncAttributeMaxDynamicSharedMemorySize, GSMEM);
    cudaFuncSetAttribute(attn_mma<true>,  cudaFuncAttributeMaxDynamicSharedMemorySize, ASMEM);
    cudaFuncSetAttribute(attn_mma<false>, cudaFuncAttributeMaxDynamicSharedMemorySize, ASMEM);

    dim3 gg(Hdim / 128, MT / 128);  // (8, 32)
    gemm_mma<true><<<gg, 256, GSMEM>>>(q, Wq, bq, gq);
    gemm_mma<true><<<gg, 256, GSMEM>>>(k, Wk, bk, gk);
    gemm_mma<true><<<gg, 256, GSMEM>>>(v, Wv, bv, gv);

    const long long atted_elems = (long long)MT * Hdim;             // 4,194,304
    const long long map_elems   = (long long)BATCH * NH * Ss * Ss;  // 134,217,728
    dim3 ga(Ss / 64, NH, BATCH);  // (32, 16, 2)
    if ((long long)out_size >= atted_elems + map_elems) {
        attn_mma<true><<<ga, 128, ASMEM>>>(out + (size_t)atted_elems);
    } else {
        attn_mma<false><<<ga, 128, ASMEM>>>(nullptr);
    }

    gemm_mma<false><<<gg, 256, GSMEM>>>(go, Wm, bm, out);
}

// round 11
// speedup vs baseline: 3.1746x; 1.0038x over previous
#include <cuda_runtime.h>
#include <cstdint>
#include <math.h>

#define Hdim  1024
#define NH    16
#define DH    64
#define BATCH 2
#define Ss    2048
#define MT    (BATCH * Ss)

// Scratch (no allocs allowed)
__device__ float g_q[MT * Hdim];
__device__ float g_k[MT * Hdim];
__device__ float g_v[MT * Hdim];
__device__ float g_o[MT * Hdim];

// ======================= helpers =======================
__device__ __forceinline__ uint32_t s2u(const void* p) {
    uint32_t a;
    asm("{ .reg .u64 t; cvta.to.shared.u64 t, %1; cvt.u32.u64 %0, t; }"
        : "=r"(a) : "l"(p));
    return a;
}
__device__ __forceinline__ float tf32r(float x) {
    uint32_t u;
    asm("cvt.rna.tf32.f32 %0, %1;" : "=r"(u) : "f"(x));
    return __uint_as_float(u);
}
__device__ __forceinline__ uint32_t tf32u(float x) {
    uint32_t u;
    asm("cvt.rna.tf32.f32 %0, %1;" : "=r"(u) : "f"(x));
    return u;
}
__device__ __forceinline__ void mma8(float* c, const uint32_t* a, const uint32_t* b) {
    asm volatile(
        "mma.sync.aligned.m16n8k8.row.col.f32.tf32.tf32.f32 "
        "{%0,%1,%2,%3}, {%4,%5,%6,%7}, {%8,%9}, {%0,%1,%2,%3};\n"
        : "+f"(c[0]), "+f"(c[1]), "+f"(c[2]), "+f"(c[3])
        : "r"(a[0]), "r"(a[1]), "r"(a[2]), "r"(a[3]), "r"(b[0]), "r"(b[1]));
}
__device__ __forceinline__ void cpa16(uint32_t dst, const void* src) {
    asm volatile("cp.async.cg.shared.global [%0], [%1], 16;" :: "r"(dst), "l"(src));
}
#define CPCOMMIT() asm volatile("cp.async.commit_group;" ::: "memory")
#define CPWAIT0()  asm volatile("cp.async.wait_group 0;" ::: "memory")
#define CPWAIT1()  asm volatile("cp.async.wait_group 1;" ::: "memory")

__device__ __forceinline__ float sigm(float x) {
    return __fdividef(1.0f, 1.0f + __expf(-0.125f * x));
}

// ======================= projection GEMM (cp.async 2-stage) =======================
#define GP  36
#define GST (128 * GP)
#define GSMEM (4 * GST * 4)

template <bool RND>
__global__ void __launch_bounds__(256, 2) gemm_mma(
    const float* __restrict__ A, const float* __restrict__ W,
    const float* __restrict__ bias, float* __restrict__ out)
{
    extern __shared__ float gsm[];
    float* As = gsm;             // [2][GST]
    float* Bs = gsm + 2 * GST;   // [2][GST]

    const int tid = threadIdx.x, wid = tid >> 5, lane = tid & 31;
    const int qr = lane >> 2, qk = lane & 3;
    const int wr = (wid >> 1) * 32, wc = (wid & 1) * 64;
    const int m0 = blockIdx.y * 128, n0 = blockIdx.x * 128;
    const int lr = tid >> 3, lc4 = (tid & 7) * 4;

    auto issue = [&](int kc, int st) {
        const float* Ap = A + (size_t)m0 * Hdim + kc * 32;
        const float* Wp = W + (size_t)n0 * Hdim + kc * 32;
        const uint32_t ab = s2u(As + st * GST), bb = s2u(Bs + st * GST);
#pragma unroll
        for (int p = 0; p < 4; p++) {
            const int r = lr + p * 32;
            const uint32_t so = (uint32_t)(r * GP + lc4) * 4;
            cpa16(ab + so, Ap + (size_t)r * Hdim + lc4);
            cpa16(bb + so, Wp + (size_t)r * Hdim + lc4);
        }
        CPCOMMIT();
    };

    float c[2][8][4];
#pragma unroll
    for (int mi = 0; mi < 2; mi++)
#pragma unroll
        for (int ni = 0; ni < 8; ni++)
#pragma unroll
            for (int j = 0; j < 4; j++) c[mi][ni][j] = 0.0f;

    issue(0, 0);
    for (int kc = 0; kc < 32; kc++) {
        if (kc < 31) { issue(kc + 1, (kc + 1) & 1); CPWAIT1(); }
        else         { CPWAIT0(); }
        __syncthreads();
        const float* Abuf = As + (kc & 1) * GST;
        const float* Bbuf = Bs + (kc & 1) * GST;
#pragma unroll
        for (int ks = 0; ks < 4; ks++) {
            uint32_t af[2][4], bf[8][2];
#pragma unroll
            for (int mi = 0; mi < 2; mi++) {
                const float* ap = &Abuf[(wr + 16 * mi + qr) * GP + 8 * ks + qk];
                af[mi][0] = tf32u(ap[0]);
                af[mi][1] = tf32u(ap[8 * GP]);
                af[mi][2] = tf32u(ap[4]);
                af[mi][3] = tf32u(ap[8 * GP + 4]);
            }
#pragma unroll
            for (int ni = 0; ni < 8; ni++) {
                const float* bp = &Bbuf[(wc + 8 * ni + qr) * GP + 8 * ks + qk];
                bf[ni][0] = tf32u(bp[0]);
                bf[ni][1] = tf32u(bp[4]);
            }
#pragma unroll
            for (int mi = 0; mi < 2; mi++)
#pragma unroll
                for (int ni = 0; ni < 8; ni++)
                    mma8(c[mi][ni], af[mi], bf[ni]);
        }
        __syncthreads();
    }

#pragma unroll
    for (int mi = 0; mi < 2; mi++) {
        const int row = m0 + wr + 16 * mi + qr;
#pragma unroll
        for (int ni = 0; ni < 8; ni++) {
            const int col = n0 + wc + 8 * ni + 2 * qk;
            const float b0 = bias[col], b1 = bias[col + 1];
            float o00 = c[mi][ni][0] + b0, o01 = c[mi][ni][1] + b1;
            float o10 = c[mi][ni][2] + b0, o11 = c[mi][ni][3] + b1;
            if (RND) { o00 = tf32r(o00); o01 = tf32r(o01);
                       o10 = tf32r(o10); o11 = tf32r(o11); }
            *(float2*)(out + (size_t)row * Hdim + col) = make_float2(o00, o01);
            *(float2*)(out + (size_t)(row + 8) * Hdim + col) = make_float2(o10, o11);
        }
    }
}

// ======================= fused sigmoid attention (no-P-smem) =======================
// Grid (32, NH, BATCH), 128 thr (4 warps), 64 q-rows/CTA, key tiles of 128.
// Warp = 16 q-rows x all 128 key cols. Q in registers. P stays in registers:
// S C-frag == PV A-frag under key permutation l -> (l&1 ? 4+l/2 : l/2), applied
// to V's smem row placement. Smem = K 32K + V 32K = 64KB -> 3 CTAs/SM.
#define AV2   (128 * 64)
#define ASMEM (2 * 128 * 64 * 4)

template <bool WM>
__global__ void __launch_bounds__(128, 3) attn_mma(float* __restrict__ att)
{
    extern __shared__ float smr[];
    float* Ks = smr;
    float* Vs = smr + AV2;

    const int tid = threadIdx.x, wid = tid >> 5, lane = tid & 31;
    const int qr = lane >> 2, qk = lane & 3;
    const int b = blockIdx.z, h = blockIdx.y, r0 = blockIdx.x * 64;
    const int wrS = 16 * wid;

    const float* qb = g_q + (size_t)(b * Ss + r0) * Hdim + h * DH;
    const float* kb = g_k + (size_t)(b * Ss) * Hdim + h * DH;
    const float* vb = g_v + (size_t)(b * Ss) * Hdim + h * DH;

    const uint32_t ksb = s2u(Ks), vsb = s2u(Vs);

    auto issueK = [&](int t) {
        const float* src = kb + (size_t)t * 128 * Hdim;
#pragma unroll
        for (int p = 0; p < 16; p++) {
            const int j = tid + p * 128;
            const int row = j >> 4, c4 = (j & 15) * 4;
            const int cs = c4 ^ ((row & 7) << 2);
            cpa16(ksb + (uint32_t)(row * 64 + cs) * 4, src + (size_t)row * Hdim + c4);
        }
        CPCOMMIT();
    };
    auto issueV = [&](int t) {
        const float* src = vb + (size_t)t * 128 * Hdim;
#pragma unroll
        for (int p = 0; p < 16; p++) {
            const int j = tid + p * 128;
            const int row = j >> 4, c4 = (j & 15) * 4;
            const int l = row & 7;
            const int prow = (row & ~7) | ((l & 1) ? 4 + (l >> 1) : (l >> 1));
            const int cs = c4 ^ ((prow & 7) << 2);
            cpa16(vsb + (uint32_t)(prow * 64 + cs) * 4, src + (size_t)row * Hdim + c4);
        }
        CPCOMMIT();
    };

    issueK(0);
    issueV(0);

    // Q fragments in registers (g_q already tf32-rounded)
    uint32_t qf[8][4];
    {
        const float* q0 = qb + (size_t)(wrS + qr) * Hdim;
        const float* q1 = q0 + 8 * (size_t)Hdim;
#pragma unroll
        for (int ks = 0; ks < 8; ks++) {
            qf[ks][0] = __float_as_uint(q0[8 * ks + qk]);
            qf[ks][1] = __float_as_uint(q1[8 * ks + qk]);
            qf[ks][2] = __float_as_uint(q0[8 * ks + qk + 4]);
            qf[ks][3] = __float_as_uint(q1[8 * ks + qk + 4]);
        }
    }

    float o[8][4];
#pragma unroll
    for (int ni = 0; ni < 8; ni++)
#pragma unroll
        for (int j = 0; j < 4; j++) o[ni][j] = 0.0f;

    for (int kt = 0; kt < 16; kt++) {
        CPWAIT1();        // K(kt) landed; V(kt) may still be in flight
        __syncthreads();

        // ---- S = Q @ K^T : warp tile 16 x 128 ----
        float s[16][4];
#pragma unroll
        for (int ni = 0; ni < 16; ni++)
#pragma unroll
            for (int j = 0; j < 4; j++) s[ni][j] = 0.0f;

#pragma unroll
        for (int ks = 0; ks < 8; ks++) {
            const int c0 = (8 * ks + qk) ^ (qr << 2);
            const int c1 = c0 ^ 4;
#pragma unroll
            for (int ni = 0; ni < 16; ni++) {
                const int br = 8 * ni + qr;
                uint32_t bf[2];
                bf[0] = __float_as_uint(Ks[br * 64 + c0]);
                bf[1] = __float_as_uint(Ks[br * 64 + c1]);
                mma8(s[ni], qf[ks], bf);
            }
        }
        __syncthreads();  // Ks consumed

        if (kt < 15) issueK(kt + 1);

        // ---- sigmoid -> att_map; convert P in registers ----
        {
            const int rr = wrS + qr;
#pragma unroll
            for (int ni = 0; ni < 16; ni++) {
                const float p0 = sigm(s[ni][0]);
                const float p1 = sigm(s[ni][1]);
                const float p2 = sigm(s[ni][2]);
                const float p3 = sigm(s[ni][3]);
                if (WM) {
                    const int cc = 8 * ni + 2 * qk;
                    size_t base = ((size_t)((b * NH + h) * Ss) + r0 + rr) * Ss
                                + (size_t)kt * 128 + cc;
                    *(float2*)(att + base) = make_float2(p0, p1);
                    *(float2*)(att + base + 8 * (size_t)Ss) = make_float2(p2, p3);
                }
                s[ni][0] = tf32r(p0);
                s[ni][1] = tf32r(p1);
                s[ni][2] = tf32r(p2);
                s[ni][3] = tf32r(p3);
            }
        }

        if (kt < 15) { CPWAIT1(); }  // V(kt) landed (K(kt+1) in flight)
        else         { CPWAIT0(); }
        __syncthreads();  // Vs visible

        // ---- O += P @ V : A-frag = {c0, c2, c1, c3} of S, V rows permuted ----
#pragma unroll
        for (int ks = 0; ks < 16; ks++) {
            uint32_t af[4];
            af[0] = __float_as_uint(s[ks][0]);
            af[1] = __float_as_uint(s[ks][2]);
            af[2] = __float_as_uint(s[ks][1]);
            af[3] = __float_as_uint(s[ks][3]);
            const int vr0 = 8 * ks + qk, vr1 = vr0 + 4;
            const int sv0 = qk << 2, sv1 = (qk + 4) << 2;
#pragma unroll
            for (int ni = 0; ni < 8; ni++) {
                const int vc = 8 * ni + qr;
                uint32_t bf[2];
                bf[0] = __float_as_uint(Vs[vr0 * 64 + (vc ^ sv0)]);
                bf[1] = __float_as_uint(Vs[vr1 * 64 + (vc ^ sv1)]);
                mma8(o[ni], af, bf);
            }
        }
        __syncthreads();  // Vs consumed

        if (kt < 15) issueV(kt + 1);
    }

    // ---- write O ----
    const int row = r0 + wrS + qr;
    float* ob = g_o + (size_t)(b * Ss + row) * Hdim + h * DH;
#pragma unroll
    for (int ni = 0; ni < 8; ni++) {
        const int col = 8 * ni + 2 * qk;
        *(float2*)(ob + col) = make_float2(o[ni][0], o[ni][1]);
        *(float2*)(ob + 8 * (size_t)Hdim + col) = make_float2(o[ni][2], o[ni][3]);
    }
}

// ---------------------------------------------------------------------------
extern "C" void kernel_launch(void* const* d_in, const int* in_sizes, int n_in,
                              void* d_out, int out_size)
{
    (void)in_sizes; (void)n_in;
    const float* v  = (const float*)d_in[0];
    const float* k  = (const float*)d_in[1];
    const float* q  = (const float*)d_in[2];
    const float* Wv = (const float*)d_in[3];
    const float* bv = (const float*)d_in[4];
    const float* Wk = (const float*)d_in[5];
    const float* bk = (const float*)d_in[6];
    const float* Wq = (const float*)d_in[7];
    const float* bq = (const float*)d_in[8];
    const float* Wm = (const float*)d_in[9];
    const float* bm = (const float*)d_in[10];
    float* out = (float*)d_out;

    float *gq, *gk, *gv, *go;
    cudaGetSymbolAddress((void**)&gq, g_q);
    cudaGetSymbolAddress((void**)&gk, g_k);
    cudaGetSymbolAddress((void**)&gv, g_v);
    cudaGetSymbolAddress((void**)&go, g_o);

    cudaFuncSetAttribute(gemm_mma<true>,  cudaFuncAttributeMaxDynamicSharedMemorySize, GSMEM);
    cudaFuncSetAttribute(gemm_mma<false>, cudaFuncAttributeMaxDynamicSharedMemorySize, GSMEM);
    cudaFuncSetAttribute(attn_mma<true>,  cudaFuncAttributeMaxDynamicSharedMemorySize, ASMEM);
    cudaFuncSetAttribute(attn_mma<false>, cudaFuncAttributeMaxDynamicSharedMemorySize, ASMEM);

    dim3 gg(Hdim / 128, MT / 128);  // (8, 32)
    gemm_mma<true><<<gg, 256, GSMEM>>>(q, Wq, bq, gq);
    gemm_mma<true><<<gg, 256, GSMEM>>>(k, Wk, bk, gk);
    gemm_mma<true><<<gg, 256, GSMEM>>>(v, Wv, bv, gv);

    const long long atted_elems = (long long)MT * Hdim;             // 4,194,304
    const long long map_elems   = (long long)BATCH * NH * Ss * Ss;  // 134,217,728
    dim3 ga(Ss / 64, NH, BATCH);  // (32, 16, 2)
    if ((long long)out_size >= atted_elems + map_elems) {
        attn_mma<true><<<ga, 128, ASMEM>>>(out + (size_t)atted_elems);
    } else {
        attn_mma<false><<<ga, 128, ASMEM>>>(nullptr);
    }

    gemm_mma<false><<<gg, 256, GSMEM>>>(go, Wm, bm, out);
}

// round 12
// speedup vs baseline: 3.5329x; 1.1129x over previous
#include <cuda_runtime.h>
#include <cstdint>
#include <math.h>

#define Hdim  1024
#define NH    16
#define DH    64
#define BATCH 2
#define Ss    2048
#define MT    (BATCH * Ss)

// Scratch (no allocs allowed). g_v holds V TRANSPOSED: [b*1024 + h*64 + d][token]
__device__ float g_q[MT * Hdim];
__device__ float g_k[MT * Hdim];
__device__ float g_v[MT * Hdim];
__device__ float g_o[MT * Hdim];

// ======================= helpers =======================
__device__ __forceinline__ uint32_t s2u(const void* p) {
    uint32_t a;
    asm("{ .reg .u64 t; cvta.to.shared.u64 t, %1; cvt.u32.u64 %0, t; }"
        : "=r"(a) : "l"(p));
    return a;
}
__device__ __forceinline__ float tf32r(float x) {
    uint32_t u;
    asm("cvt.rna.tf32.f32 %0, %1;" : "=r"(u) : "f"(x));
    return __uint_as_float(u);
}
__device__ __forceinline__ uint32_t tf32u(float x) {
    uint32_t u;
    asm("cvt.rna.tf32.f32 %0, %1;" : "=r"(u) : "f"(x));
    return u;
}
__device__ __forceinline__ void mma8(float* c, const uint32_t* a, const uint32_t* b) {
    asm volatile(
        "mma.sync.aligned.m16n8k8.row.col.f32.tf32.tf32.f32 "
        "{%0,%1,%2,%3}, {%4,%5,%6,%7}, {%8,%9}, {%0,%1,%2,%3};\n"
        : "+f"(c[0]), "+f"(c[1]), "+f"(c[2]), "+f"(c[3])
        : "r"(a[0]), "r"(a[1]), "r"(a[2]), "r"(a[3]), "r"(b[0]), "r"(b[1]));
}
__device__ __forceinline__ void cpa16(uint32_t dst, const void* src) {
    asm volatile("cp.async.cg.shared.global [%0], [%1], 16;" :: "r"(dst), "l"(src));
}
#define CPCOMMIT() asm volatile("cp.async.commit_group;" ::: "memory")
#define CPWAIT0()  asm volatile("cp.async.wait_group 0;" ::: "memory")
#define CPWAIT1()  asm volatile("cp.async.wait_group 1;" ::: "memory")

__device__ __forceinline__ float sigm(float x) {
    return __fdividef(1.0f, 1.0f + __expf(-0.125f * x));
}

// ======================= projection GEMM (cp.async 2-stage) =======================
// MODE 0: plain fp32 out (final proj). MODE 1: tf32-rounded out (Q, K).
// MODE 3: tf32-rounded + TRANSPOSED out for V: out[(b*1024 + col)*2048 + token].
#define GP  36
#define GST (128 * GP)
#define GSMEM (4 * GST * 4)

template <int MODE>
__global__ void __launch_bounds__(256, 2) gemm_mma(
    const float* __restrict__ A, const float* __restrict__ W,
    const float* __restrict__ bias, float* __restrict__ out)
{
    extern __shared__ float gsm[];
    float* As = gsm;             // [2][GST]
    float* Bs = gsm + 2 * GST;   // [2][GST]

    const int tid = threadIdx.x, wid = tid >> 5, lane = tid & 31;
    const int qr = lane >> 2, qk = lane & 3;
    const int wr = (wid >> 1) * 32, wc = (wid & 1) * 64;
    const int m0 = blockIdx.y * 128, n0 = blockIdx.x * 128;
    const int lr = tid >> 3, lc4 = (tid & 7) * 4;

    auto issue = [&](int kc, int st) {
        const float* Ap = A + (size_t)m0 * Hdim + kc * 32;
        const float* Wp = W + (size_t)n0 * Hdim + kc * 32;
        const uint32_t ab = s2u(As + st * GST), bb = s2u(Bs + st * GST);
#pragma unroll
        for (int p = 0; p < 4; p++) {
            const int r = lr + p * 32;
            const uint32_t so = (uint32_t)(r * GP + lc4) * 4;
            cpa16(ab + so, Ap + (size_t)r * Hdim + lc4);
            cpa16(bb + so, Wp + (size_t)r * Hdim + lc4);
        }
        CPCOMMIT();
    };

    float c[2][8][4];
#pragma unroll
    for (int mi = 0; mi < 2; mi++)
#pragma unroll
        for (int ni = 0; ni < 8; ni++)
#pragma unroll
            for (int j = 0; j < 4; j++) c[mi][ni][j] = 0.0f;

    issue(0, 0);
    for (int kc = 0; kc < 32; kc++) {
        if (kc < 31) { issue(kc + 1, (kc + 1) & 1); CPWAIT1(); }
        else         { CPWAIT0(); }
        __syncthreads();
        const float* Abuf = As + (kc & 1) * GST;
        const float* Bbuf = Bs + (kc & 1) * GST;
#pragma unroll
        for (int ks = 0; ks < 4; ks++) {
            uint32_t af[2][4], bf[8][2];
#pragma unroll
            for (int mi = 0; mi < 2; mi++) {
                const float* ap = &Abuf[(wr + 16 * mi + qr) * GP + 8 * ks + qk];
                af[mi][0] = tf32u(ap[0]);
                af[mi][1] = tf32u(ap[8 * GP]);
                af[mi][2] = tf32u(ap[4]);
                af[mi][3] = tf32u(ap[8 * GP + 4]);
            }
#pragma unroll
            for (int ni = 0; ni < 8; ni++) {
                const float* bp = &Bbuf[(wc + 8 * ni + qr) * GP + 8 * ks + qk];
                bf[ni][0] = tf32u(bp[0]);
                bf[ni][1] = tf32u(bp[4]);
            }
#pragma unroll
            for (int mi = 0; mi < 2; mi++)
#pragma unroll
                for (int ni = 0; ni < 8; ni++)
                    mma8(c[mi][ni], af[mi], bf[ni]);
        }
        __syncthreads();
    }

#pragma unroll
    for (int mi = 0; mi < 2; mi++) {
        const int row = m0 + wr + 16 * mi + qr;
#pragma unroll
        for (int ni = 0; ni < 8; ni++) {
            const int col = n0 + wc + 8 * ni + 2 * qk;
            const float b0 = bias[col], b1 = bias[col + 1];
            float o00 = c[mi][ni][0] + b0, o01 = c[mi][ni][1] + b1;
            float o10 = c[mi][ni][2] + b0, o11 = c[mi][ni][3] + b1;
            if (MODE != 0) { o00 = tf32r(o00); o01 = tf32r(o01);
                             o10 = tf32r(o10); o11 = tf32r(o11); }
            if (MODE == 3) {
                const int bq = row >> 11;
                const size_t t0 = (size_t)(row & 2047);
                float* ob = out + (size_t)(bq * 1024 + col) * 2048;
                ob[t0]            = o00;
                ob[t0 + 8]        = o10;
                ob[2048 + t0]     = o01;
                ob[2048 + t0 + 8] = o11;
            } else {
                *(float2*)(out + (size_t)row * Hdim + col) = make_float2(o00, o01);
                *(float2*)(out + (size_t)(row + 8) * Hdim + col) = make_float2(o10, o11);
            }
        }
    }
}

// ======================= fused sigmoid attention (LDS.64 frags) =======================
// Grid (32, NH, BATCH), 128 thr (4 warps), 64 q-rows/CTA, key tiles of 128.
// Effective k-order sigma(kappa) = (kappa<4 ? 2k : 2(k-4)+1) in both MMAs makes every
// B-fragment pair adjacent: K pairs (d 2qk,2qk+1) in [key][d] layout; V pairs
// (keys 2qk,2qk+1) in d-major layout (g_v written transposed by its GEMM).
// 32B-chunk XOR swizzle (chunk ^ ((row&3)<<1)) => conflict-free LDS.64.
// Smem: K 32K + V 32K = 64KB -> 3 CTAs/SM.
#define AV2   (128 * 64)
#define ASMEM (2 * 128 * 64 * 4)

template <bool WM>
__global__ void __launch_bounds__(128, 3) attn_mma(float* __restrict__ att)
{
    extern __shared__ float smr[];
    float* Ks = smr;            // [128 keys][64 d]
    float* Vs = smr + AV2;      // [64 d][128 keys]

    const int tid = threadIdx.x, wid = tid >> 5, lane = tid & 31;
    const int qr = lane >> 2, qk = lane & 3;
    const int b = blockIdx.z, h = blockIdx.y, r0 = blockIdx.x * 64;
    const int wrS = 16 * wid;

    const float* qb = g_q + (size_t)(b * Ss + r0) * Hdim + h * DH;
    const float* kb = g_k + (size_t)(b * Ss) * Hdim + h * DH;
    const float* vb = g_v + (size_t)(b * 1024 + h * DH) * 2048;  // transposed V

    const uint32_t ksb = s2u(Ks), vsb = s2u(Vs);

    auto issueK = [&](int t) {
        const float* src = kb + (size_t)t * 128 * Hdim;
#pragma unroll
        for (int p = 0; p < 16; p++) {
            const int j = tid + p * 128;
            const int row = j >> 4, cch = j & 15;           // 16B chunks, 16 per row
            const int cs = cch ^ ((row & 3) << 1);
            cpa16(ksb + (uint32_t)(row * 64 + cs * 4) * 4,
                  src + (size_t)row * Hdim + cch * 4);
        }
        CPCOMMIT();
    };
    auto issueV = [&](int t) {
        const float* src = vb + (size_t)t * 128;
#pragma unroll
        for (int p = 0; p < 16; p++) {
            const int j = tid + p * 128;
            const int d = j >> 5, cch = j & 31;             // 32 chunks per d-row
            const int cs = cch ^ ((d & 3) << 1);
            cpa16(vsb + (uint32_t)(d * 128 + cs * 4) * 4,
                  src + (size_t)d * 2048 + cch * 4);
        }
        CPCOMMIT();
    };

    issueK(0);
    issueV(0);

    // Q fragments in registers, indexed in sigma order: kappa=qk -> d=2qk, kappa=qk+4 -> d=2qk+1
    uint32_t qf[8][4];
    {
        const float* q0 = qb + (size_t)(wrS + qr) * Hdim;
        const float* q1 = q0 + 8 * (size_t)Hdim;
#pragma unroll
        for (int ks = 0; ks < 8; ks++) {
            const float2 a0 = *(const float2*)(q0 + 8 * ks + 2 * qk);
            const float2 a1 = *(const float2*)(q1 + 8 * ks + 2 * qk);
            qf[ks][0] = __float_as_uint(a0.x);
            qf[ks][1] = __float_as_uint(a1.x);
            qf[ks][2] = __float_as_uint(a0.y);
            qf[ks][3] = __float_as_uint(a1.y);
        }
    }

    float o[8][4];
#pragma unroll
    for (int ni = 0; ni < 8; ni++)
#pragma unroll
        for (int j = 0; j < 4; j++) o[ni][j] = 0.0f;

    for (int kt = 0; kt < 16; kt++) {
        CPWAIT1();        // K(kt) landed; V(kt) may still be in flight
        __syncthreads();

        // ---- S = Q @ K^T : warp tile 16 x 128, K frags via LDS.64 ----
        float s[16][4];
#pragma unroll
        for (int ni = 0; ni < 16; ni++)
#pragma unroll
            for (int j = 0; j < 4; j++) s[ni][j] = 0.0f;

#pragma unroll
        for (int ks = 0; ks < 8; ks++) {
            const int dpair = 8 * ks + 2 * qk;
#pragma unroll
            for (int ni = 0; ni < 16; ni++) {
                const int br = 8 * ni + qr;
                const float2 kk =
                    *(const float2*)&Ks[br * 64 + (dpair ^ ((br & 3) << 3))];
                uint32_t bf[2];
                bf[0] = __float_as_uint(kk.x);
                bf[1] = __float_as_uint(kk.y);
                mma8(s[ni], qf[ks], bf);
            }
        }
        __syncthreads();  // Ks consumed

        if (kt < 15) issueK(kt + 1);

        // ---- sigmoid -> att_map; P stays in registers ----
        {
            const int rr = wrS + qr;
#pragma unroll
            for (int ni = 0; ni < 16; ni++) {
                const float p0 = sigm(s[ni][0]);
                const float p1 = sigm(s[ni][1]);
                const float p2 = sigm(s[ni][2]);
                const float p3 = sigm(s[ni][3]);
                if (WM) {
                    const int cc = 8 * ni + 2 * qk;
                    size_t base = ((size_t)((b * NH + h) * Ss) + r0 + rr) * Ss
                                + (size_t)kt * 128 + cc;
                    *(float2*)(att + base) = make_float2(p0, p1);
                    *(float2*)(att + base + 8 * (size_t)Ss) = make_float2(p2, p3);
                }
                s[ni][0] = tf32r(p0);
                s[ni][1] = tf32r(p1);
                s[ni][2] = tf32r(p2);
                s[ni][3] = tf32r(p3);
            }
        }

        if (kt < 15) { CPWAIT1(); }  // V(kt) landed (K(kt+1) in flight)
        else         { CPWAIT0(); }
        __syncthreads();  // Vs visible

        // ---- O += P @ V : A = {c0,c2,c1,c3} of S; V frags via LDS.64 ----
#pragma unroll
        for (int ks = 0; ks < 16; ks++) {
            uint32_t af[4];
            af[0] = __float_as_uint(s[ks][0]);
            af[1] = __float_as_uint(s[ks][2]);
            af[2] = __float_as_uint(s[ks][1]);
            af[3] = __float_as_uint(s[ks][3]);
            const int kpair = 8 * ks + 2 * qk;
#pragma unroll
            for (int ni = 0; ni < 8; ni++) {
                const int vc = 8 * ni + qr;  // d row of Vs
                const float2 vv =
                    *(const float2*)&Vs[vc * 128 + (kpair ^ ((vc & 3) << 3))];
                uint32_t bf[2];
                bf[0] = __float_as_uint(vv.x);
                bf[1] = __float_as_uint(vv.y);
                mma8(o[ni], af, bf);
            }
        }
        __syncthreads();  // Vs consumed

        if (kt < 15) issueV(kt + 1);
    }

    // ---- write O (natural layout for the final GEMM) ----
    const int row = r0 + wrS + qr;
    float* ob = g_o + (size_t)(b * Ss + row) * Hdim + h * DH;
#pragma unroll
    for (int ni = 0; ni < 8; ni++) {
        const int col = 8 * ni + 2 * qk;
        *(float2*)(ob + col) = make_float2(o[ni][0], o[ni][1]);
        *(float2*)(ob + 8 * (size_t)Hdim + col) = make_float2(o[ni][2], o[ni][3]);
    }
}

// ---------------------------------------------------------------------------
extern "C" void kernel_launch(void* const* d_in, const int* in_sizes, int n_in,
                              void* d_out, int out_size)
{
    (void)in_sizes; (void)n_in;
    const float* v  = (const float*)d_in[0];
    const float* k  = (const float*)d_in[1];
    const float* q  = (const float*)d_in[2];
    const float* Wv = (const float*)d_in[3];
    const float* bv = (const float*)d_in[4];
    const float* Wk = (const float*)d_in[5];
    const float* bk = (const float*)d_in[6];
    const float* Wq = (const float*)d_in[7];
    const float* bq = (const float*)d_in[8];
    const float* Wm = (const float*)d_in[9];
    const float* bm = (const float*)d_in[10];
    float* out = (float*)d_out;

    float *gq, *gk, *gv, *go;
    cudaGetSymbolAddress((void**)&gq, g_q);
    cudaGetSymbolAddress((void**)&gk, g_k);
    cudaGetSymbolAddress((void**)&gv, g_v);
    cudaGetSymbolAddress((void**)&go, g_o);

    cudaFuncSetAttribute(gemm_mma<0>, cudaFuncAttributeMaxDynamicSharedMemorySize, GSMEM);
    cudaFuncSetAttribute(gemm_mma<1>, cudaFuncAttributeMaxDynamicSharedMemorySize, GSMEM);
    cudaFuncSetAttribute(gemm_mma<3>, cudaFuncAttributeMaxDynamicSharedMemorySize, GSMEM);
    cudaFuncSetAttribute(attn_mma<true>,  cudaFuncAttributeMaxDynamicSharedMemorySize, ASMEM);
    cudaFuncSetAttribute(attn_mma<false>, cudaFuncAttributeMaxDynamicSharedMemorySize, ASMEM);

    dim3 gg(Hdim / 128, MT / 128);  // (8, 32)
    gemm_mma<1><<<gg, 256, GSMEM>>>(q, Wq, bq, gq);
    gemm_mma<1><<<gg, 256, GSMEM>>>(k, Wk, bk, gk);
    gemm_mma<3><<<gg, 256, GSMEM>>>(v, Wv, bv, gv);  // writes g_v transposed

    const long long atted_elems = (long long)MT * Hdim;             // 4,194,304
    const long long map_elems   = (long long)BATCH * NH * Ss * Ss;  // 134,217,728
    dim3 ga(Ss / 64, NH, BATCH);  // (32, 16, 2)
    if ((long long)out_size >= atted_elems + map_elems) {
        attn_mma<true><<<ga, 128, ASMEM>>>(out + (size_t)atted_elems);
    } else {
        attn_mma<false><<<ga, 128, ASMEM>>>(nullptr);
    }

    gemm_mma<0><<<gg, 256, GSMEM>>>(go, Wm, bm, out);
}

// round 13
// speedup vs baseline: 3.5349x; 1.0006x over previous
#include <cuda_runtime.h>
#include <cstdint>
#include <math.h>

#define Hdim  1024
#define NH    16
#define DH    64
#define BATCH 2
#define Ss    2048
#define MT    (BATCH * Ss)

// Scratch (no allocs allowed). g_v holds V TRANSPOSED: [b*1024 + h*64 + d][token]
__device__ float g_q[MT * Hdim];
__device__ float g_k[MT * Hdim];
__device__ float g_v[MT * Hdim];
__device__ float g_o[MT * Hdim];

// ======================= helpers =======================
__device__ __forceinline__ uint32_t s2u(const void* p) {
    uint32_t a;
    asm("{ .reg .u64 t; cvta.to.shared.u64 t, %1; cvt.u32.u64 %0, t; }"
        : "=r"(a) : "l"(p));
    return a;
}
__device__ __forceinline__ float tf32r(float x) {
    uint32_t u;
    asm("cvt.rna.tf32.f32 %0, %1;" : "=r"(u) : "f"(x));
    return __uint_as_float(u);
}
__device__ __forceinline__ uint32_t tf32u(float x) {
    uint32_t u;
    asm("cvt.rna.tf32.f32 %0, %1;" : "=r"(u) : "f"(x));
    return u;
}
__device__ __forceinline__ void mma8(float* c, const uint32_t* a, const uint32_t* b) {
    asm volatile(
        "mma.sync.aligned.m16n8k8.row.col.f32.tf32.tf32.f32 "
        "{%0,%1,%2,%3}, {%4,%5,%6,%7}, {%8,%9}, {%0,%1,%2,%3};\n"
        : "+f"(c[0]), "+f"(c[1]), "+f"(c[2]), "+f"(c[3])
        : "r"(a[0]), "r"(a[1]), "r"(a[2]), "r"(a[3]), "r"(b[0]), "r"(b[1]));
}
__device__ __forceinline__ void cpa16(uint32_t dst, const void* src) {
    asm volatile("cp.async.cg.shared.global [%0], [%1], 16;" :: "r"(dst), "l"(src));
}
#define CPCOMMIT() asm volatile("cp.async.commit_group;" ::: "memory")
#define CPWAIT0()  asm volatile("cp.async.wait_group 0;" ::: "memory")
#define CPWAIT1()  asm volatile("cp.async.wait_group 1;" ::: "memory")

__device__ __forceinline__ float sigm(float x) {
    return __fdividef(1.0f, 1.0f + __expf(-0.125f * x));
}

// ======================= projection GEMM (cp.async 2-stage) =======================
// MODE 0: plain fp32 out (final proj). MODE 1: tf32-rounded out (Q, K).
// MODE 3: tf32-rounded + TRANSPOSED out for V: out[(b*1024 + col)*2048 + token].
#define GP  36
#define GST (128 * GP)
#define GSMEM (4 * GST * 4)

template <int MODE>
__global__ void __launch_bounds__(256, 2) gemm_mma(
    const float* __restrict__ A, const float* __restrict__ W,
    const float* __restrict__ bias, float* __restrict__ out)
{
    extern __shared__ float gsm[];
    float* As = gsm;             // [2][GST]
    float* Bs = gsm + 2 * GST;   // [2][GST]

    const int tid = threadIdx.x, wid = tid >> 5, lane = tid & 31;
    const int qr = lane >> 2, qk = lane & 3;
    const int wr = (wid >> 1) * 32, wc = (wid & 1) * 64;
    const int m0 = blockIdx.y * 128, n0 = blockIdx.x * 128;
    const int lr = tid >> 3, lc4 = (tid & 7) * 4;

    auto issue = [&](int kc, int st) {
        const float* Ap = A + (size_t)m0 * Hdim + kc * 32;
        const float* Wp = W + (size_t)n0 * Hdim + kc * 32;
        const uint32_t ab = s2u(As + st * GST), bb = s2u(Bs + st * GST);
#pragma unroll
        for (int p = 0; p < 4; p++) {
            const int r = lr + p * 32;
            const uint32_t so = (uint32_t)(r * GP + lc4) * 4;
            cpa16(ab + so, Ap + (size_t)r * Hdim + lc4);
            cpa16(bb + so, Wp + (size_t)r * Hdim + lc4);
        }
        CPCOMMIT();
    };

    float c[2][8][4];
#pragma unroll
    for (int mi = 0; mi < 2; mi++)
#pragma unroll
        for (int ni = 0; ni < 8; ni++)
#pragma unroll
            for (int j = 0; j < 4; j++) c[mi][ni][j] = 0.0f;

    issue(0, 0);
    for (int kc = 0; kc < 32; kc++) {
        if (kc < 31) { issue(kc + 1, (kc + 1) & 1); CPWAIT1(); }
        else         { CPWAIT0(); }
        __syncthreads();
        const float* Abuf = As + (kc & 1) * GST;
        const float* Bbuf = Bs + (kc & 1) * GST;
#pragma unroll
        for (int ks = 0; ks < 4; ks++) {
            uint32_t af[2][4], bf[8][2];
#pragma unroll
            for (int mi = 0; mi < 2; mi++) {
                const float* ap = &Abuf[(wr + 16 * mi + qr) * GP + 8 * ks + qk];
                af[mi][0] = tf32u(ap[0]);
                af[mi][1] = tf32u(ap[8 * GP]);
                af[mi][2] = tf32u(ap[4]);
                af[mi][3] = tf32u(ap[8 * GP + 4]);
            }
#pragma unroll
            for (int ni = 0; ni < 8; ni++) {
                const float* bp = &Bbuf[(wc + 8 * ni + qr) * GP + 8 * ks + qk];
                bf[ni][0] = tf32u(bp[0]);
                bf[ni][1] = tf32u(bp[4]);
            }
#pragma unroll
            for (int mi = 0; mi < 2; mi++)
#pragma unroll
                for (int ni = 0; ni < 8; ni++)
                    mma8(c[mi][ni], af[mi], bf[ni]);
        }
        __syncthreads();
    }

#pragma unroll
    for (int mi = 0; mi < 2; mi++) {
        const int row = m0 + wr + 16 * mi + qr;
#pragma unroll
        for (int ni = 0; ni < 8; ni++) {
            const int col = n0 + wc + 8 * ni + 2 * qk;
            const float b0 = bias[col], b1 = bias[col + 1];
            float o00 = c[mi][ni][0] + b0, o01 = c[mi][ni][1] + b1;
            float o10 = c[mi][ni][2] + b0, o11 = c[mi][ni][3] + b1;
            if (MODE != 0) { o00 = tf32r(o00); o01 = tf32r(o01);
                             o10 = tf32r(o10); o11 = tf32r(o11); }
            if (MODE == 3) {
                const int bq = row >> 11;
                const size_t t0 = (size_t)(row & 2047);
                float* ob = out + (size_t)(bq * 1024 + col) * 2048;
                ob[t0]            = o00;
                ob[t0 + 8]        = o10;
                ob[2048 + t0]     = o01;
                ob[2048 + t0 + 8] = o11;
            } else {
                *(float2*)(out + (size_t)row * Hdim + col) = make_float2(o00, o01);
                *(float2*)(out + (size_t)(row + 8) * Hdim + col) = make_float2(o10, o11);
            }
        }
    }
}

// ======================= fused sigmoid attention (LDS.64 frags) =======================
// Grid (32, NH, BATCH), 128 thr (4 warps), 64 q-rows/CTA, key tiles of 128.
// Effective k-order sigma(kappa) = (kappa<4 ? 2k : 2(k-4)+1) in both MMAs makes every
// B-fragment pair adjacent: K pairs (d 2qk,2qk+1) in [key][d] layout; V pairs
// (keys 2qk,2qk+1) in d-major layout (g_v written transposed by its GEMM).
// 32B-chunk XOR swizzle (chunk ^ ((row&3)<<1)) => conflict-free LDS.64.
// Smem: K 32K + V 32K = 64KB -> 3 CTAs/SM.
#define AV2   (128 * 64)
#define ASMEM (2 * 128 * 64 * 4)

template <bool WM>
__global__ void __launch_bounds__(128, 3) attn_mma(float* __restrict__ att)
{
    extern __shared__ float smr[];
    float* Ks = smr;            // [128 keys][64 d]
    float* Vs = smr + AV2;      // [64 d][128 keys]

    const int tid = threadIdx.x, wid = tid >> 5, lane = tid & 31;
    const int qr = lane >> 2, qk = lane & 3;
    const int b = blockIdx.z, h = blockIdx.y, r0 = blockIdx.x * 64;
    const int wrS = 16 * wid;

    const float* qb = g_q + (size_t)(b * Ss + r0) * Hdim + h * DH;
    const float* kb = g_k + (size_t)(b * Ss) * Hdim + h * DH;
    const float* vb = g_v + (size_t)(b * 1024 + h * DH) * 2048;  // transposed V

    const uint32_t ksb = s2u(Ks), vsb = s2u(Vs);

    auto issueK = [&](int t) {
        const float* src = kb + (size_t)t * 128 * Hdim;
#pragma unroll
        for (int p = 0; p < 16; p++) {
            const int j = tid + p * 128;
            const int row = j >> 4, cch = j & 15;           // 16B chunks, 16 per row
            const int cs = cch ^ ((row & 3) << 1);
            cpa16(ksb + (uint32_t)(row * 64 + cs * 4) * 4,
                  src + (size_t)row * Hdim + cch * 4);
        }
        CPCOMMIT();
    };
    auto issueV = [&](int t) {
        const float* src = vb + (size_t)t * 128;
#pragma unroll
        for (int p = 0; p < 16; p++) {
            const int j = tid + p * 128;
            const int d = j >> 5, cch = j & 31;             // 32 chunks per d-row
            const int cs = cch ^ ((d & 3) << 1);
            cpa16(vsb + (uint32_t)(d * 128 + cs * 4) * 4,
                  src + (size_t)d * 2048 + cch * 4);
        }
        CPCOMMIT();
    };

    issueK(0);
    issueV(0);

    // Q fragments in registers, indexed in sigma order: kappa=qk -> d=2qk, kappa=qk+4 -> d=2qk+1
    uint32_t qf[8][4];
    {
        const float* q0 = qb + (size_t)(wrS + qr) * Hdim;
        const float* q1 = q0 + 8 * (size_t)Hdim;
#pragma unroll
        for (int ks = 0; ks < 8; ks++) {
            const float2 a0 = *(const float2*)(q0 + 8 * ks + 2 * qk);
            const float2 a1 = *(const float2*)(q1 + 8 * ks + 2 * qk);
            qf[ks][0] = __float_as_uint(a0.x);
            qf[ks][1] = __float_as_uint(a1.x);
            qf[ks][2] = __float_as_uint(a0.y);
            qf[ks][3] = __float_as_uint(a1.y);
        }
    }

    float o[8][4];
#pragma unroll
    for (int ni = 0; ni < 8; ni++)
#pragma unroll
        for (int j = 0; j < 4; j++) o[ni][j] = 0.0f;

    for (int kt = 0; kt < 16; kt++) {
        CPWAIT1();        // K(kt) landed; V(kt) may still be in flight
        __syncthreads();

        // ---- S = Q @ K^T : warp tile 16 x 128, K frags via LDS.64 ----
        float s[16][4];
#pragma unroll
        for (int ni = 0; ni < 16; ni++)
#pragma unroll
            for (int j = 0; j < 4; j++) s[ni][j] = 0.0f;

#pragma unroll
        for (int ks = 0; ks < 8; ks++) {
            const int dpair = 8 * ks + 2 * qk;
#pragma unroll
            for (int ni = 0; ni < 16; ni++) {
                const int br = 8 * ni + qr;
                const float2 kk =
                    *(const float2*)&Ks[br * 64 + (dpair ^ ((br & 3) << 3))];
                uint32_t bf[2];
                bf[0] = __float_as_uint(kk.x);
                bf[1] = __float_as_uint(kk.y);
                mma8(s[ni], qf[ks], bf);
            }
        }
        __syncthreads();  // Ks consumed

        if (kt < 15) issueK(kt + 1);

        // ---- sigmoid -> att_map; P stays in registers ----
        {
            const int rr = wrS + qr;
#pragma unroll
            for (int ni = 0; ni < 16; ni++) {
                const float p0 = sigm(s[ni][0]);
                const float p1 = sigm(s[ni][1]);
                const float p2 = sigm(s[ni][2]);
                const float p3 = sigm(s[ni][3]);
                if (WM) {
                    const int cc = 8 * ni + 2 * qk;
                    size_t base = ((size_t)((b * NH + h) * Ss) + r0 + rr) * Ss
                                + (size_t)kt * 128 + cc;
                    *(float2*)(att + base) = make_float2(p0, p1);
                    *(float2*)(att + base + 8 * (size_t)Ss) = make_float2(p2, p3);
                }
                s[ni][0] = tf32r(p0);
                s[ni][1] = tf32r(p1);
                s[ni][2] = tf32r(p2);
                s[ni][3] = tf32r(p3);
            }
        }

        if (kt < 15) { CPWAIT1(); }  // V(kt) landed (K(kt+1) in flight)
        else         { CPWAIT0(); }
        __syncthreads();  // Vs visible

        // ---- O += P @ V : A = {c0,c2,c1,c3} of S; V frags via LDS.64 ----
#pragma unroll
        for (int ks = 0; ks < 16; ks++) {
            uint32_t af[4];
            af[0] = __float_as_uint(s[ks][0]);
            af[1] = __float_as_uint(s[ks][2]);
            af[2] = __float_as_uint(s[ks][1]);
            af[3] = __float_as_uint(s[ks][3]);
            const int kpair = 8 * ks + 2 * qk;
#pragma unroll
            for (int ni = 0; ni < 8; ni++) {
                const int vc = 8 * ni + qr;  // d row of Vs
                const float2 vv =
                    *(const float2*)&Vs[vc * 128 + (kpair ^ ((vc & 3) << 3))];
                uint32_t bf[2];
                bf[0] = __float_as_uint(vv.x);
                bf[1] = __float_as_uint(vv.y);
                mma8(o[ni], af, bf);
            }
        }
        __syncthreads();  // Vs consumed

        if (kt < 15) issueV(kt + 1);
    }

    // ---- write O (natural layout for the final GEMM) ----
    const int row = r0 + wrS + qr;
    float* ob = g_o + (size_t)(b * Ss + row) * Hdim + h * DH;
#pragma unroll
    for (int ni = 0; ni < 8; ni++) {
        const int col = 8 * ni + 2 * qk;
        *(float2*)(ob + col) = make_float2(o[ni][0], o[ni][1]);
        *(float2*)(ob + 8 * (size_t)Hdim + col) = make_float2(o[ni][2], o[ni][3]);
    }
}

// ---------------------------------------------------------------------------
extern "C" void kernel_launch(void* const* d_in, const int* in_sizes, int n_in,
                              void* d_out, int out_size)
{
    (void)in_sizes; (void)n_in;
    const float* v  = (const float*)d_in[0];
    const float* k  = (const float*)d_in[1];
    const float* q  = (const float*)d_in[2];
    const float* Wv = (const float*)d_in[3];
    const float* bv = (const float*)d_in[4];
    const float* Wk = (const float*)d_in[5];
    const float* bk = (const float*)d_in[6];
    const float* Wq = (const float*)d_in[7];
    const float* bq = (const float*)d_in[8];
    const float* Wm = (const float*)d_in[9];
    const float* bm = (const float*)d_in[10];
    float* out = (float*)d_out;

    float *gq, *gk, *gv, *go;
    cudaGetSymbolAddress((void**)&gq, g_q);
    cudaGetSymbolAddress((void**)&gk, g_k);
    cudaGetSymbolAddress((void**)&gv, g_v);
    cudaGetSymbolAddress((void**)&go, g_o);

    cudaFuncSetAttribute(gemm_mma<0>, cudaFuncAttributeMaxDynamicSharedMemorySize, GSMEM);
    cudaFuncSetAttribute(gemm_mma<1>, cudaFuncAttributeMaxDynamicSharedMemorySize, GSMEM);
    cudaFuncSetAttribute(gemm_mma<3>, cudaFuncAttributeMaxDynamicSharedMemorySize, GSMEM);
    cudaFuncSetAttribute(attn_mma<true>,  cudaFuncAttributeMaxDynamicSharedMemorySize, ASMEM);
    cudaFuncSetAttribute(attn_mma<false>, cudaFuncAttributeMaxDynamicSharedMemorySize, ASMEM);

    dim3 gg(Hdim / 128, MT / 128);  // (8, 32)
    gemm_mma<1><<<gg, 256, GSMEM>>>(q, Wq, bq, gq);
    gemm_mma<1><<<gg, 256, GSMEM>>>(k, Wk, bk, gk);
    gemm_mma<3><<<gg, 256, GSMEM>>>(v, Wv, bv, gv);  // writes g_v transposed

    const long long atted_elems = (long long)MT * Hdim;             // 4,194,304
    const long long map_elems   = (long long)BATCH * NH * Ss * Ss;  // 134,217,728
    dim3 ga(Ss / 64, NH, BATCH);  // (32, 16, 2)
    if ((long long)out_size >= atted_elems + map_elems) {
        attn_mma<true><<<ga, 128, ASMEM>>>(out + (size_t)atted_elems);
    } else {
        attn_mma<false><<<ga, 128, ASMEM>>>(nullptr);
    }

    gemm_mma<0><<<gg, 256, GSMEM>>>(go, Wm, bm, out);
}

// round 14
// speedup vs baseline: 3.5400x; 1.0014x over previous
#include <cuda_runtime.h>
#include <cstdint>
#include <math.h>

#define Hdim  1024
#define NH    16
#define DH    64
#define BATCH 2
#define Ss    2048
#define MT    (BATCH * Ss)

// Scratch (no allocs allowed). g_v holds V TRANSPOSED: [b*1024 + h*64 + d][token]
__device__ float g_q[MT * Hdim];
__device__ float g_k[MT * Hdim];
__device__ float g_v[MT * Hdim];
__device__ float g_o[MT * Hdim];

// ======================= helpers =======================
__device__ __forceinline__ uint32_t s2u(const void* p) {
    uint32_t a;
    asm("{ .reg .u64 t; cvta.to.shared.u64 t, %1; cvt.u32.u64 %0, t; }"
        : "=r"(a) : "l"(p));
    return a;
}
__device__ __forceinline__ float tf32r(float x) {
    uint32_t u;
    asm("cvt.rna.tf32.f32 %0, %1;" : "=r"(u) : "f"(x));
    return __uint_as_float(u);
}
__device__ __forceinline__ uint32_t tf32u(float x) {
    uint32_t u;
    asm("cvt.rna.tf32.f32 %0, %1;" : "=r"(u) : "f"(x));
    return u;
}
__device__ __forceinline__ void mma8(float* c, const uint32_t* a, const uint32_t* b) {
    asm volatile(
        "mma.sync.aligned.m16n8k8.row.col.f32.tf32.tf32.f32 "
        "{%0,%1,%2,%3}, {%4,%5,%6,%7}, {%8,%9}, {%0,%1,%2,%3};\n"
        : "+f"(c[0]), "+f"(c[1]), "+f"(c[2]), "+f"(c[3])
        : "r"(a[0]), "r"(a[1]), "r"(a[2]), "r"(a[3]), "r"(b[0]), "r"(b[1]));
}
__device__ __forceinline__ void cpa16(uint32_t dst, const void* src) {
    asm volatile("cp.async.cg.shared.global [%0], [%1], 16;" :: "r"(dst), "l"(src));
}
#define CPCOMMIT() asm volatile("cp.async.commit_group;" ::: "memory")
#define CPWAIT0()  asm volatile("cp.async.wait_group 0;" ::: "memory")
#define CPWAIT1()  asm volatile("cp.async.wait_group 1;" ::: "memory")

__device__ __forceinline__ float sigm(float x) {
    return __fdividef(1.0f, 1.0f + __expf(-0.125f * x));
}

// ======================= projection GEMM (cp.async 2-stage) =======================
// MODE 0: plain fp32 out (final proj). MODE 1: tf32-rounded out (Q, K).
// MODE 3: tf32-rounded + TRANSPOSED out for V: out[(b*1024 + col)*2048 + token].
#define GP  36
#define GST (128 * GP)
#define GSMEM (4 * GST * 4)

template <int MODE>
__global__ void __launch_bounds__(256, 2) gemm_mma(
    const float* __restrict__ A, const float* __restrict__ W,
    const float* __restrict__ bias, float* __restrict__ out)
{
    extern __shared__ float gsm[];
    float* As = gsm;             // [2][GST]
    float* Bs = gsm + 2 * GST;   // [2][GST]

    const int tid = threadIdx.x, wid = tid >> 5, lane = tid & 31;
    const int qr = lane >> 2, qk = lane & 3;
    const int wr = (wid >> 1) * 32, wc = (wid & 1) * 64;
    const int m0 = blockIdx.y * 128, n0 = blockIdx.x * 128;
    const int lr = tid >> 3, lc4 = (tid & 7) * 4;

    auto issue = [&](int kc, int st) {
        const float* Ap = A + (size_t)m0 * Hdim + kc * 32;
        const float* Wp = W + (size_t)n0 * Hdim + kc * 32;
        const uint32_t ab = s2u(As + st * GST), bb = s2u(Bs + st * GST);
#pragma unroll
        for (int p = 0; p < 4; p++) {
            const int r = lr + p * 32;
            const uint32_t so = (uint32_t)(r * GP + lc4) * 4;
            cpa16(ab + so, Ap + (size_t)r * Hdim + lc4);
            cpa16(bb + so, Wp + (size_t)r * Hdim + lc4);
        }
        CPCOMMIT();
    };

    float c[2][8][4];
#pragma unroll
    for (int mi = 0; mi < 2; mi++)
#pragma unroll
        for (int ni = 0; ni < 8; ni++)
#pragma unroll
            for (int j = 0; j < 4; j++) c[mi][ni][j] = 0.0f;

    issue(0, 0);
    for (int kc = 0; kc < 32; kc++) {
        if (kc < 31) { issue(kc + 1, (kc + 1) & 1); CPWAIT1(); }
        else         { CPWAIT0(); }
        __syncthreads();
        const float* Abuf = As + (kc & 1) * GST;
        const float* Bbuf = Bs + (kc & 1) * GST;
#pragma unroll
        for (int ks = 0; ks < 4; ks++) {
            uint32_t af[2][4], bf[8][2];
#pragma unroll
            for (int mi = 0; mi < 2; mi++) {
                const float* ap = &Abuf[(wr + 16 * mi + qr) * GP + 8 * ks + qk];
                af[mi][0] = tf32u(ap[0]);
                af[mi][1] = tf32u(ap[8 * GP]);
                af[mi][2] = tf32u(ap[4]);
                af[mi][3] = tf32u(ap[8 * GP + 4]);
            }
#pragma unroll
            for (int ni = 0; ni < 8; ni++) {
                const float* bp = &Bbuf[(wc + 8 * ni + qr) * GP + 8 * ks + qk];
                bf[ni][0] = tf32u(bp[0]);
                bf[ni][1] = tf32u(bp[4]);
            }
#pragma unroll
            for (int mi = 0; mi < 2; mi++)
#pragma unroll
                for (int ni = 0; ni < 8; ni++)
                    mma8(c[mi][ni], af[mi], bf[ni]);
        }
        __syncthreads();
    }

#pragma unroll
    for (int mi = 0; mi < 2; mi++) {
        const int row = m0 + wr + 16 * mi + qr;
#pragma unroll
        for (int ni = 0; ni < 8; ni++) {
            const int col = n0 + wc + 8 * ni + 2 * qk;
            const float b0 = bias[col], b1 = bias[col + 1];
            float o00 = c[mi][ni][0] + b0, o01 = c[mi][ni][1] + b1;
            float o10 = c[mi][ni][2] + b0, o11 = c[mi][ni][3] + b1;
            if (MODE != 0) { o00 = tf32r(o00); o01 = tf32r(o01);
                             o10 = tf32r(o10); o11 = tf32r(o11); }
            if (MODE == 3) {
                const int bq = row >> 11;
                const size_t t0 = (size_t)(row & 2047);
                float* ob = out + (size_t)(bq * 1024 + col) * 2048;
                ob[t0]            = o00;
                ob[t0 + 8]        = o10;
                ob[2048 + t0]     = o01;
                ob[2048 + t0 + 8] = o11;
            } else {
                *(float2*)(out + (size_t)row * Hdim + col) = make_float2(o00, o01);
                *(float2*)(out + (size_t)(row + 8) * Hdim + col) = make_float2(o10, o11);
            }
        }
    }
}

// ======================= fused sigmoid attention (LDS.64 frags) =======================
// Grid (32, NH, BATCH), 128 thr (4 warps), 64 q-rows/CTA, key tiles of 128.
// Effective k-order sigma(kappa) = (kappa<4 ? 2k : 2(k-4)+1) in both MMAs makes every
// B-fragment pair adjacent: K pairs (d 2qk,2qk+1) in [key][d] layout; V pairs
// (keys 2qk,2qk+1) in d-major layout (g_v written transposed by its GEMM).
// 32B-chunk XOR swizzle (chunk ^ ((row&3)<<1)) => conflict-free LDS.64.
// Smem: K 32K + V 32K = 64KB -> 3 CTAs/SM.
#define AV2   (128 * 64)
#define ASMEM (2 * 128 * 64 * 4)

template <bool WM>
__global__ void __launch_bounds__(128, 3) attn_mma(float* __restrict__ att)
{
    extern __shared__ float smr[];
    float* Ks = smr;            // [128 keys][64 d]
    float* Vs = smr + AV2;      // [64 d][128 keys]

    const int tid = threadIdx.x, wid = tid >> 5, lane = tid & 31;
    const int qr = lane >> 2, qk = lane & 3;
    const int b = blockIdx.z, h = blockIdx.y, r0 = blockIdx.x * 64;
    const int wrS = 16 * wid;

    const float* qb = g_q + (size_t)(b * Ss + r0) * Hdim + h * DH;
    const float* kb = g_k + (size_t)(b * Ss) * Hdim + h * DH;
    const float* vb = g_v + (size_t)(b * 1024 + h * DH) * 2048;  // transposed V

    const uint32_t ksb = s2u(Ks), vsb = s2u(Vs);

    auto issueK = [&](int t) {
        const float* src = kb + (size_t)t * 128 * Hdim;
#pragma unroll
        for (int p = 0; p < 16; p++) {
            const int j = tid + p * 128;
            const int row = j >> 4, cch = j & 15;           // 16B chunks, 16 per row
            const int cs = cch ^ ((row & 3) << 1);
            cpa16(ksb + (uint32_t)(row * 64 + cs * 4) * 4,
                  src + (size_t)row * Hdim + cch * 4);
        }
        CPCOMMIT();
    };
    auto issueV = [&](int t) {
        const float* src = vb + (size_t)t * 128;
#pragma unroll
        for (int p = 0; p < 16; p++) {
            const int j = tid + p * 128;
            const int d = j >> 5, cch = j & 31;             // 32 chunks per d-row
            const int cs = cch ^ ((d & 3) << 1);
            cpa16(vsb + (uint32_t)(d * 128 + cs * 4) * 4,
                  src + (size_t)d * 2048 + cch * 4);
        }
        CPCOMMIT();
    };

    issueK(0);
    issueV(0);

    // Q fragments in registers, indexed in sigma order: kappa=qk -> d=2qk, kappa=qk+4 -> d=2qk+1
    uint32_t qf[8][4];
    {
        const float* q0 = qb + (size_t)(wrS + qr) * Hdim;
        const float* q1 = q0 + 8 * (size_t)Hdim;
#pragma unroll
        for (int ks = 0; ks < 8; ks++) {
            const float2 a0 = *(const float2*)(q0 + 8 * ks + 2 * qk);
            const float2 a1 = *(const float2*)(q1 + 8 * ks + 2 * qk);
            qf[ks][0] = __float_as_uint(a0.x);
            qf[ks][1] = __float_as_uint(a1.x);
            qf[ks][2] = __float_as_uint(a0.y);
            qf[ks][3] = __float_as_uint(a1.y);
        }
    }

    float o[8][4];
#pragma unroll
    for (int ni = 0; ni < 8; ni++)
#pragma unroll
        for (int j = 0; j < 4; j++) o[ni][j] = 0.0f;

    for (int kt = 0; kt < 16; kt++) {
        CPWAIT1();        // K(kt) landed; V(kt) may still be in flight
        __syncthreads();

        // ---- S = Q @ K^T : warp tile 16 x 128, K frags via LDS.64 ----
        float s[16][4];
#pragma unroll
        for (int ni = 0; ni < 16; ni++)
#pragma unroll
            for (int j = 0; j < 4; j++) s[ni][j] = 0.0f;

#pragma unroll
        for (int ks = 0; ks < 8; ks++) {
            const int dpair = 8 * ks + 2 * qk;
#pragma unroll
            for (int ni = 0; ni < 16; ni++) {
                const int br = 8 * ni + qr;
                const float2 kk =
                    *(const float2*)&Ks[br * 64 + (dpair ^ ((br & 3) << 3))];
                uint32_t bf[2];
                bf[0] = __float_as_uint(kk.x);
                bf[1] = __float_as_uint(kk.y);
                mma8(s[ni], qf[ks], bf);
            }
        }
        __syncthreads();  // Ks consumed

        if (kt < 15) issueK(kt + 1);

        // ---- sigmoid -> att_map; P stays in registers ----
        {
            const int rr = wrS + qr;
#pragma unroll
            for (int ni = 0; ni < 16; ni++) {
                const float p0 = sigm(s[ni][0]);
                const float p1 = sigm(s[ni][1]);
                const float p2 = sigm(s[ni][2]);
                const float p3 = sigm(s[ni][3]);
                if (WM) {
                    const int cc = 8 * ni + 2 * qk;
                    size_t base = ((size_t)((b * NH + h) * Ss) + r0 + rr) * Ss
                                + (size_t)kt * 128 + cc;
                    *(float2*)(att + base) = make_float2(p0, p1);
                    *(float2*)(att + base + 8 * (size_t)Ss) = make_float2(p2, p3);
                }
                s[ni][0] = tf32r(p0);
                s[ni][1] = tf32r(p1);
                s[ni][2] = tf32r(p2);
                s[ni][3] = tf32r(p3);
            }
        }

        if (kt < 15) { CPWAIT1(); }  // V(kt) landed (K(kt+1) in flight)
        else         { CPWAIT0(); }
        __syncthreads();  // Vs visible

        // ---- O += P @ V : A = {c0,c2,c1,c3} of S; V frags via LDS.64 ----
#pragma unroll
        for (int ks = 0; ks < 16; ks++) {
            uint32_t af[4];
            af[0] = __float_as_uint(s[ks][0]);
            af[1] = __float_as_uint(s[ks][2]);
            af[2] = __float_as_uint(s[ks][1]);
            af[3] = __float_as_uint(s[ks][3]);
            const int kpair = 8 * ks + 2 * qk;
#pragma unroll
            for (int ni = 0; ni < 8; ni++) {
                const int vc = 8 * ni + qr;  // d row of Vs
                const float2 vv =
                    *(const float2*)&Vs[vc * 128 + (kpair ^ ((vc & 3) << 3))];
                uint32_t bf[2];
                bf[0] = __float_as_uint(vv.x);
                bf[1] = __float_as_uint(vv.y);
                mma8(o[ni], af, bf);
            }
        }
        __syncthreads();  // Vs consumed

        if (kt < 15) issueV(kt + 1);
    }

    // ---- write O (natural layout for the final GEMM) ----
    const int row = r0 + wrS + qr;
    float* ob = g_o + (size_t)(b * Ss + row) * Hdim + h * DH;
#pragma unroll
    for (int ni = 0; ni < 8; ni++) {
        const int col = 8 * ni + 2 * qk;
        *(float2*)(ob + col) = make_float2(o[ni][0], o[ni][1]);
        *(float2*)(ob + 8 * (size_t)Hdim + col) = make_float2(o[ni][2], o[ni][3]);
    }
}

// ---------------------------------------------------------------------------
extern "C" void kernel_launch(void* const* d_in, const int* in_sizes, int n_in,
                              void* d_out, int out_size)
{
    (void)in_sizes; (void)n_in;
    const float* v  = (const float*)d_in[0];
    const float* k  = (const float*)d_in[1];
    const float* q  = (const float*)d_in[2];
    const float* Wv = (const float*)d_in[3];
    const float* bv = (const float*)d_in[4];
    const float* Wk = (const float*)d_in[5];
    const float* bk = (const float*)d_in[6];
    const float* Wq = (const float*)d_in[7];
    const float* bq = (const float*)d_in[8];
    const float* Wm = (const float*)d_in[9];
    const float* bm = (const float*)d_in[10];
    float* out = (float*)d_out;

    float *gq, *gk, *gv, *go;
    cudaGetSymbolAddress((void**)&gq, g_q);
    cudaGetSymbolAddress((void**)&gk, g_k);
    cudaGetSymbolAddress((void**)&gv, g_v);
    cudaGetSymbolAddress((void**)&go, g_o);

    cudaFuncSetAttribute(gemm_mma<0>, cudaFuncAttributeMaxDynamicSharedMemorySize, GSMEM);
    cudaFuncSetAttribute(gemm_mma<1>, cudaFuncAttributeMaxDynamicSharedMemorySize, GSMEM);
    cudaFuncSetAttribute(gemm_mma<3>, cudaFuncAttributeMaxDynamicSharedMemorySize, GSMEM);
    cudaFuncSetAttribute(attn_mma<true>,  cudaFuncAttributeMaxDynamicSharedMemorySize, ASMEM);
    cudaFuncSetAttribute(attn_mma<false>, cudaFuncAttributeMaxDynamicSharedMemorySize, ASMEM);

    dim3 gg(Hdim / 128, MT / 128);  // (8, 32)
    gemm_mma<1><<<gg, 256, GSMEM>>>(q, Wq, bq, gq);
    gemm_mma<1><<<gg, 256, GSMEM>>>(k, Wk, bk, gk);
    gemm_mma<3><<<gg, 256, GSMEM>>>(v, Wv, bv, gv);  // writes g_v transposed

    const long long atted_elems = (long long)MT * Hdim;             // 4,194,304
    const long long map_elems   = (long long)BATCH * NH * Ss * Ss;  // 134,217,728
    dim3 ga(Ss / 64, NH, BATCH);  // (32, 16, 2)
    if ((long long)out_size >= atted_elems + map_elems) {
        attn_mma<true><<<ga, 128, ASMEM>>>(out + (size_t)atted_elems);
    } else {
        attn_mma<false><<<ga, 128, ASMEM>>>(nullptr);
    }

    gemm_mma<0><<<gg, 256, GSMEM>>>(go, Wm, bm, out);
}